// round 14
// baseline (speedup 1.0000x reference)
#include <cuda_runtime.h>
#include <cuda_fp16.h>
#include <cstdint>
#include <cstddef>

#define NN 50000
#define EE 1600000
#define DD 512

// ---------------------------------------------------------------------------
// Device scratch (no runtime alloc allowed)
// ---------------------------------------------------------------------------
__device__ __half g_A16[(size_t)NN * DD];
__device__ __half g_H1[(size_t)NN * DD];
__device__ __half g_H2[(size_t)NN * DD];
__device__ __half g_W16[(size_t)3 * DD * DD];
__device__ float  g_W23[(size_t)DD * DD];
__device__ float  g_uvec[DD];
// CSR scratch
__device__ int   g_cnt[NN];
__device__ int   g_rowptr[NN + 1];
__device__ int   g_cursor[NN];
__device__ int   g_partial[256];
__device__ int2  g_edge[EE];
__device__ float g_d[NN];
__device__ float g_e[NN];
// Pipelining state (spmm3 -> final gemm)
__device__ int   g_flags[NN];
__device__ int   g_ctrS;
__device__ int   g_ctrG;

// ---------------------------------------------------------------------------
// Helpers
// ---------------------------------------------------------------------------
__device__ __forceinline__ uint32_t smem_to_u32(const void* p) {
    uint32_t a;
    asm("{ .reg .u64 t; cvta.to.shared.u64 t, %1; cvt.u32.u64 %0, t; }" : "=r"(a) : "l"(p));
    return a;
}

__device__ __forceinline__ void cp16(uint32_t dst, const void* src, bool valid) {
    int sz = valid ? 16 : 0;
    asm volatile("cp.async.cg.shared.global [%0], [%1], 16, %2;"
                 :: "r"(dst), "l"(src), "r"(sz) : "memory");
}
#define CP_COMMIT() asm volatile("cp.async.commit_group;" ::: "memory")
#define CP_WAIT(n)  asm volatile("cp.async.wait_group %0;" :: "n"(n) : "memory")

__device__ __forceinline__ void mma_f16(float* d, const uint32_t* a, const uint32_t* b) {
    asm volatile("mma.sync.aligned.m16n8k16.row.col.f32.f16.f16.f32 "
                 "{%0,%1,%2,%3}, {%4,%5,%6,%7}, {%8,%9}, {%0,%1,%2,%3};"
                 : "+f"(d[0]), "+f"(d[1]), "+f"(d[2]), "+f"(d[3])
                 : "r"(a[0]), "r"(a[1]), "r"(a[2]), "r"(a[3]), "r"(b[0]), "r"(b[1]));
}

__device__ __forceinline__ void ldsm_x4(uint32_t* r, uint32_t addr) {
    asm volatile("ldmatrix.sync.aligned.m8n8.x4.shared.b16 {%0,%1,%2,%3}, [%4];"
                 : "=r"(r[0]), "=r"(r[1]), "=r"(r[2]), "=r"(r[3]) : "r"(addr));
}
__device__ __forceinline__ void ldsm_x2(uint32_t* r, uint32_t addr) {
    asm volatile("ldmatrix.sync.aligned.m8n8.x2.shared.b16 {%0,%1}, [%2];"
                 : "=r"(r[0]), "=r"(r[1]) : "r"(addr));
}

// L2 cache policies via createpolicy (portable cache_hint form, any width)
__device__ __forceinline__ uint64_t pol_evict_last() {
    uint64_t p;
    asm("createpolicy.fractional.L2::evict_last.b64 %0, 1.0;" : "=l"(p));
    return p;
}
__device__ __forceinline__ uint64_t pol_evict_first() {
    uint64_t p;
    asm("createpolicy.fractional.L2::evict_first.b64 %0, 1.0;" : "=l"(p));
    return p;
}

__device__ __forceinline__ uint2 ldg_gather(const __half* p, uint64_t pol) {
    uint2 v;
    asm volatile("ld.global.nc.L2::cache_hint.v2.u32 {%0,%1}, [%2], %3;"
                 : "=r"(v.x), "=r"(v.y) : "l"(p), "l"(pol));
    return v;
}
__device__ __forceinline__ uint32_t ldg_gather32(const __half* p, uint64_t pol) {
    uint32_t v;
    asm volatile("ld.global.nc.L2::cache_hint.b32 %0, [%1], %2;"
                 : "=r"(v) : "l"(p), "l"(pol));
    return v;
}
__device__ __forceinline__ float4 ldg_once_f4(const float* p, uint64_t pol) {
    float4 v;
    asm volatile("ld.global.L2::cache_hint.v4.f32 {%0,%1,%2,%3}, [%4], %5;"
                 : "=f"(v.x), "=f"(v.y), "=f"(v.z), "=f"(v.w) : "l"(p), "l"(pol));
    return v;
}
__device__ __forceinline__ void stg_resident(__half* p, uint2 v, uint64_t pol) {
    asm volatile("st.global.L2::cache_hint.v2.u32 [%0], {%1,%2}, %3;"
                 :: "l"(p), "r"(v.x), "r"(v.y), "l"(pol) : "memory");
}
__device__ __forceinline__ void stg_resident32(__half* p, uint32_t v, uint64_t pol) {
    asm volatile("st.global.L2::cache_hint.u32 [%0], %1, %2;"
                 :: "l"(p), "r"(v), "l"(pol) : "memory");
}

// ---------------------------------------------------------------------------
// GEMM CTA body (ldmatrix + fp16 mma, fp32 accum)
// ---------------------------------------------------------------------------
#define BK 32
#define RSTRIDE 20
#define TILE_WORDS (128 * RSTRIDE)
#define STAGE_WORDS (2 * TILE_WORDS)
#define GEMM_SMEM (2 * STAGE_WORDS * 4)   // 40960 bytes
#define NBY ((NN + 127) / 128)            // 391
#define G1  (4 * NBY)                     // CTAs per N=512 GEMM: 1564

__device__ __forceinline__ void gemm_load_stage(
    uint32_t sbase, int stage, const __half* A, const __half* B,
    int bm, int bn, int kc, int M, int tid)
{
    const uint32_t st = sbase + (uint32_t)stage * STAGE_WORDS * 4;
    const int r0 = tid >> 2;
    const int r1 = r0 + 64;
    const int j  = tid & 3;
    const uint32_t d0 = st + (uint32_t)(r0 * RSTRIDE + j * 4) * 4;
    const uint32_t d1 = st + (uint32_t)(r1 * RSTRIDE + j * 4) * 4;
    const size_t koff = (size_t)kc * BK + j * 8;
    const bool v0 = (bm + r0) < M;
    const bool v1 = (bm + r1) < M;

    cp16(d0,                  A + (size_t)(bm + r0) * DD + koff, v0);
    cp16(d1,                  A + (size_t)(bm + r1) * DD + koff, v1);
    cp16(d0 + TILE_WORDS * 4, B + (size_t)(bn + r0) * DD + koff, true);
    cp16(d1 + TILE_WORDS * 4, B + (size_t)(bn + r1) * DD + koff, true);
}

__device__ void gemm_cta(
    int g, uint32_t* s,
    const __half* __restrict__ A, const __half* __restrict__ B,
    const float* __restrict__ bias,
    const float* __restrict__ rowE, const float* __restrict__ colU,
    const float* __restrict__ rowD, const float* __restrict__ colB3,
    float* __restrict__ C, __half* __restrict__ C16, int ldc, int M)
{
    const uint32_t sbase = smem_to_u32(s);
    const int tid  = threadIdx.x;
    const int warp = tid >> 5;
    const int lane = tid & 31;
    const int wm   = (warp & 1) * 64;
    const int wn   = (warp >> 1) * 32;
    const int grp  = lane >> 2;
    const int qd   = lane & 3;
    const int bm = (g >> 2) * 128;
    const int n0 = (g & 3) * 128;

    const int arow = wm + (lane & 15);
    const int acol = (lane >> 4) * 4;
    const int brow = wn + (lane & 7);
    const int bcol = ((lane >> 3) & 1) * 4;

    float acc[4][4][4];
    #pragma unroll
    for (int i = 0; i < 4; i++)
        #pragma unroll
        for (int j = 0; j < 4; j++)
            #pragma unroll
            for (int q = 0; q < 4; q++) acc[i][j][q] = 0.f;

    gemm_load_stage(sbase, 0, A, B, bm, n0, 0, M, tid);
    CP_COMMIT();

    #pragma unroll 1
    for (int kc = 0; kc < DD / BK; kc++) {
        if (kc + 1 < DD / BK) {
            gemm_load_stage(sbase, (kc + 1) & 1, A, B, bm, n0, kc + 1, M, tid);
            CP_COMMIT();
            CP_WAIT(1);
        } else {
            CP_WAIT(0);
        }
        __syncthreads();

        const uint32_t As_b = sbase + (uint32_t)(kc & 1) * STAGE_WORDS * 4;
        const uint32_t Bs_b = As_b + TILE_WORDS * 4;

        #pragma unroll
        for (int ks = 0; ks < 2; ks++) {
            const int kw = ks * 8;
            uint32_t ah[4][4];
            #pragma unroll
            for (int mi = 0; mi < 4; mi++)
                ldsm_x4(ah[mi], As_b + (uint32_t)((arow + mi * 16) * RSTRIDE + kw + acol) * 4);
            #pragma unroll
            for (int nj = 0; nj < 4; nj++) {
                uint32_t bh[2];
                ldsm_x2(bh, Bs_b + (uint32_t)((brow + nj * 8) * RSTRIDE + kw + bcol) * 4);
                #pragma unroll
                for (int mi = 0; mi < 4; mi++)
                    mma_f16(acc[mi][nj], ah[mi], bh);
            }
        }
        __syncthreads();
    }

    const uint64_t pl = pol_evict_last();
    #pragma unroll
    for (int mi = 0; mi < 4; mi++) {
        const int gr = bm + wm + mi * 16 + grp;
        float e0 = 0.f, d0v = 0.f, e1 = 0.f, d1v = 0.f;
        if (rowE) {
            if (gr < M)     { e0 = rowE[gr];     d0v = rowD[gr]; }
            if (gr + 8 < M) { e1 = rowE[gr + 8]; d1v = rowD[gr + 8]; }
        }
        #pragma unroll
        for (int nj = 0; nj < 4; nj++) {
            const int gc = n0 + wn + nj * 8 + qd * 2;
            float2 add0, add1;
            if (rowE) {
                const float2 uu = *(const float2*)(colU + gc);
                const float2 b3 = *(const float2*)(colB3 + gc);
                add0 = make_float2(e0 * uu.x + d0v * b3.x, e0 * uu.y + d0v * b3.y);
                add1 = make_float2(e1 * uu.x + d1v * b3.x, e1 * uu.y + d1v * b3.y);
            } else {
                const float2 bz = *(const float2*)(bias + gc);
                add0 = bz; add1 = bz;
            }
            float2 o0 = {acc[mi][nj][0] + add0.x, acc[mi][nj][1] + add0.y};
            float2 o1 = {acc[mi][nj][2] + add1.x, acc[mi][nj][3] + add1.y};
            if (C16) {
                __half2 h0 = __float22half2_rn(o0);
                __half2 h1 = __float22half2_rn(o1);
                if (gr < M)
                    stg_resident32(C16 + (size_t)gr * ldc + gc, *(uint32_t*)&h0, pl);
                if (gr + 8 < M)
                    stg_resident32(C16 + (size_t)(gr + 8) * ldc + gc, *(uint32_t*)&h1, pl);
            } else {
                if (gr < M)     *(float2*)(C + (size_t)gr * ldc + gc) = o0;
                if (gr + 8 < M) *(float2*)(C + (size_t)(gr + 8) * ldc + gc) = o1;
            }
        }
    }
}

// ---------------------------------------------------------------------------
// fusedAB: a0-GEMM CTAs + H1-GEMM CTAs + scatter CTAs in one grid
// ---------------------------------------------------------------------------
__global__ void __launch_bounds__(256, 2) fusedAB(
    const __half* __restrict__ A, const __half* __restrict__ B0,
    const __half* __restrict__ B1,
    const float* __restrict__ bias0, const float* __restrict__ bias1,
    float* __restrict__ C, __half* __restrict__ H1, int M,
    const int* __restrict__ rows, const int* __restrict__ cols,
    const float* __restrict__ vals, int* __restrict__ cursor,
    int2* __restrict__ edge, int E)
{
    extern __shared__ uint32_t s[];
    const int bid = blockIdx.x;
    if (bid < G1) {
        gemm_cta(bid, s, A, B0, bias0,
                 nullptr, nullptr, nullptr, nullptr, C, nullptr, 1024, M);
    } else if (bid < 2 * G1) {
        gemm_cta(bid - G1, s, A, B1, bias1,
                 nullptr, nullptr, nullptr, nullptr, nullptr, H1, DD, M);
    } else {
        int e = (bid - 2 * G1) * 256 + threadIdx.x;
        if (e < E) {
            int r = rows[e];
            int p = atomicAdd(&cursor[r], 1);
            edge[p] = make_int2(cols[e], __float_as_int(vals[e]));
        }
    }
}

// ---------------------------------------------------------------------------
// Parallel scan: scan_part + scan_add2 (top scan inlined per block)
// ---------------------------------------------------------------------------
#define SCB 256

__global__ void __launch_bounds__(SCB) scan_part(
    const int* __restrict__ cnt, int* __restrict__ row_ptr,
    int* __restrict__ partial, int M)
{
    __shared__ int sm[SCB];
    const int tid = threadIdx.x;
    const int i = blockIdx.x * SCB + tid;
    int v = (i < M) ? cnt[i] : 0;
    sm[tid] = v;
    __syncthreads();
    #pragma unroll
    for (int off = 1; off < SCB; off <<= 1) {
        int t = (tid >= off) ? sm[tid - off] : 0;
        __syncthreads();
        sm[tid] += t;
        __syncthreads();
    }
    if (i < M) row_ptr[i] = sm[tid] - v;
    if (tid == SCB - 1) partial[blockIdx.x] = sm[tid];
}

__global__ void __launch_bounds__(SCB) scan_add2(
    int* __restrict__ row_ptr, int* __restrict__ cursor,
    const int* __restrict__ partial, int M, int E, int nblk)
{
    __shared__ int sm[SCB];
    __shared__ int ex[SCB];
    const int tid = threadIdx.x;
    int v = (tid < nblk) ? partial[tid] : 0;
    sm[tid] = v;
    __syncthreads();
    #pragma unroll
    for (int off = 1; off < SCB; off <<= 1) {
        int t = (tid >= off) ? sm[tid - off] : 0;
        __syncthreads();
        sm[tid] += t;
        __syncthreads();
    }
    ex[tid] = sm[tid] - v;
    __syncthreads();
    const int off_b = ex[blockIdx.x];
    const int i = blockIdx.x * SCB + tid;
    if (i < M) {
        int val = row_ptr[i] + off_b;
        row_ptr[i] = val;
        cursor[i]  = val;
    }
    if (i == 0) row_ptr[M] = E;
}

// ---------------------------------------------------------------------------
// fp16 CSR SpMM core: 4-edge unrolled, evict_last gathers, fp32 accum
// (128-thread variant: 8 bytes/thread)
// ---------------------------------------------------------------------------
__device__ __forceinline__ void fma_h4(float4& acc, float v, uint2 r) {
    const float2 a0 = __half22float2(*(const __half2*)&r.x);
    const float2 a1 = __half22float2(*(const __half2*)&r.y);
    acc.x = fmaf(v, a0.x, acc.x); acc.y = fmaf(v, a0.y, acc.y);
    acc.z = fmaf(v, a1.x, acc.z); acc.w = fmaf(v, a1.y, acc.w);
}

__device__ __forceinline__ float4 spmm_row_acc_h(
    const int* __restrict__ row_ptr, const int2* __restrict__ edge,
    const __half* __restrict__ in, int r, int tid, uint64_t pol)
{
    const size_t off = (size_t)tid * 4;
    int e = row_ptr[r];
    const int end = row_ptr[r + 1];
    float4 acc = {0.f, 0.f, 0.f, 0.f};

    for (; e + 4 <= end; e += 4) {
        const int2 E0 = __ldg(edge + e);
        const int2 E1 = __ldg(edge + e + 1);
        const int2 E2 = __ldg(edge + e + 2);
        const int2 E3 = __ldg(edge + e + 3);
        const uint2 R0 = ldg_gather(in + (size_t)E0.x * DD + off, pol);
        const uint2 R1 = ldg_gather(in + (size_t)E1.x * DD + off, pol);
        const uint2 R2 = ldg_gather(in + (size_t)E2.x * DD + off, pol);
        const uint2 R3 = ldg_gather(in + (size_t)E3.x * DD + off, pol);
        fma_h4(acc, __int_as_float(E0.y), R0);
        fma_h4(acc, __int_as_float(E1.y), R1);
        fma_h4(acc, __int_as_float(E2.y), R2);
        fma_h4(acc, __int_as_float(E3.y), R3);
    }
    for (; e < end; e++) {
        const int2 E0 = __ldg(edge + e);
        const uint2 R0 = ldg_gather(in + (size_t)E0.x * DD + off, pol);
        fma_h4(acc, __int_as_float(E0.y), R0);
    }
    return acc;
}

// 256-thread variant: 4 bytes/thread (used inside fusedE)
__device__ __forceinline__ float2 spmm_row_acc256(
    const int* __restrict__ row_ptr, const int2* __restrict__ edge,
    const __half* __restrict__ in, int r, int tid, uint64_t pol)
{
    const size_t off = (size_t)tid * 2;
    int e = row_ptr[r];
    const int end = row_ptr[r + 1];
    float2 acc = {0.f, 0.f};

    for (; e + 4 <= end; e += 4) {
        const int2 E0 = __ldg(edge + e);
        const int2 E1 = __ldg(edge + e + 1);
        const int2 E2 = __ldg(edge + e + 2);
        const int2 E3 = __ldg(edge + e + 3);
        const uint32_t R0 = ldg_gather32(in + (size_t)E0.x * DD + off, pol);
        const uint32_t R1 = ldg_gather32(in + (size_t)E1.x * DD + off, pol);
        const uint32_t R2 = ldg_gather32(in + (size_t)E2.x * DD + off, pol);
        const uint32_t R3 = ldg_gather32(in + (size_t)E3.x * DD + off, pol);
        float2 a;
        a = __half22float2(*(const __half2*)&R0);
        acc.x = fmaf(__int_as_float(E0.y), a.x, acc.x);
        acc.y = fmaf(__int_as_float(E0.y), a.y, acc.y);
        a = __half22float2(*(const __half2*)&R1);
        acc.x = fmaf(__int_as_float(E1.y), a.x, acc.x);
        acc.y = fmaf(__int_as_float(E1.y), a.y, acc.y);
        a = __half22float2(*(const __half2*)&R2);
        acc.x = fmaf(__int_as_float(E2.y), a.x, acc.x);
        acc.y = fmaf(__int_as_float(E2.y), a.y, acc.y);
        a = __half22float2(*(const __half2*)&R3);
        acc.x = fmaf(__int_as_float(E3.y), a.x, acc.x);
        acc.y = fmaf(__int_as_float(E3.y), a.y, acc.y);
    }
    for (; e < end; e++) {
        const int2 E0 = __ldg(edge + e);
        const uint32_t R0 = ldg_gather32(in + (size_t)E0.x * DD + off, pol);
        float2 a = __half22float2(*(const __half2*)&R0);
        acc.x = fmaf(__int_as_float(E0.y), a.x, acc.x);
        acc.y = fmaf(__int_as_float(E0.y), a.y, acc.y);
    }
    return acc;
}

__device__ __forceinline__ uint2 pack_h4(float4 v) {
    uint2 o;
    *(__half2*)&o.x = __float22half2_rn(make_float2(v.x, v.y));
    *(__half2*)&o.y = __float22half2_rn(make_float2(v.z, v.w));
    return o;
}

// fusedC: spmm_mix || rowsum_d
__global__ void __launch_bounds__(128) fusedC(
    const int* __restrict__ row_ptr, const int2* __restrict__ edge,
    const __half* __restrict__ in,
    const float* __restrict__ a0, const float* __restrict__ nvec,
    __half* __restrict__ x1, float* __restrict__ dvec, int M)
{
    const int bid = blockIdx.x;
    const int tid = threadIdx.x;
    if (bid < M) {
        const uint64_t pl = pol_evict_last();
        const uint64_t pf = pol_evict_first();
        float4 acc = spmm_row_acc_h(row_ptr, edge, in, bid, tid, pl);
        const float nv = nvec[bid];
        const float om = 1.f - nv;
        const float4 a = ldg_once_f4(a0 + (size_t)bid * 1024 + (size_t)tid * 4, pf);
        float4 o;
        o.x = a.x * nv + acc.x * om;
        o.y = a.y * nv + acc.y * om;
        o.z = a.z * nv + acc.z * om;
        o.w = a.w * nv + acc.w * om;
        stg_resident(x1 + (size_t)bid * DD + (size_t)tid * 4, pack_h4(o), pl);
    } else {
        const int r = (bid - M) * 4 + (tid >> 5);
        if (r >= M) return;
        const int lane = tid & 31;
        float acc = 0.f;
        for (int e = row_ptr[r] + lane; e < row_ptr[r + 1]; e += 32)
            acc += __int_as_float(__ldg(&edge[e].y));
        #pragma unroll
        for (int o = 16; o; o >>= 1) acc += __shfl_down_sync(0xffffffffu, acc, o);
        if (lane == 0) dvec[r] = acc;
    }
}

// fusedD: spmm (H1 = S·H2) || spmv_e || uvec
__global__ void __launch_bounds__(128) fusedD(
    const int* __restrict__ row_ptr, const int2* __restrict__ edge,
    const __half* __restrict__ in, __half* __restrict__ out,
    const float* __restrict__ dvec, float* __restrict__ evec,
    const float* __restrict__ b2, const float* __restrict__ W3,
    float* __restrict__ u, int M)
{
    const int bid = blockIdx.x;
    const int tid = threadIdx.x;
    const int UB = M + (M + 3) / 4;
    if (bid < M) {
        const uint64_t pl = pol_evict_last();
        float4 acc = spmm_row_acc_h(row_ptr, edge, in, bid, tid, pl);
        stg_resident(out + (size_t)bid * DD + (size_t)tid * 4, pack_h4(acc), pl);
    } else if (bid < UB) {
        const int r = (bid - M) * 4 + (tid >> 5);
        if (r >= M) return;
        const int lane = tid & 31;
        float acc = 0.f;
        for (int e = row_ptr[r] + lane; e < row_ptr[r + 1]; e += 32) {
            const int2 ev2 = __ldg(edge + e);
            acc = fmaf(__int_as_float(ev2.y), dvec[ev2.x], acc);
        }
        #pragma unroll
        for (int o = 16; o; o >>= 1) acc += __shfl_down_sync(0xffffffffu, acc, o);
        if (lane == 0) evec[r] = acc;
    } else {
        const int n = (bid - UB) * 128 + tid;
        float acc = 0.f;
        #pragma unroll 8
        for (int j = 0; j < DD; j++)
            acc = fmaf(b2[j], W3[j * DD + n], acc);
        u[n] = acc;
    }
}

// ---------------------------------------------------------------------------
// fusedE: persistent CTAs — phase 1: SpMM#3 rows (counter); phase 2: final
// GEMM tiles (counter + per-row readiness flags). All 296 CTAs co-resident.
// ---------------------------------------------------------------------------
#define PERSIST_CTAS 296
#define RCH 8

__global__ void __launch_bounds__(256, 2) fusedE(
    const int* __restrict__ row_ptr, const int2* __restrict__ edge,
    const __half* __restrict__ in,            // H1 (S^2 x1 input)
    __half* __restrict__ A16,                 // output: S^3 x1 (fp16)
    volatile int* __restrict__ flags,
    int* __restrict__ ctrS, int* __restrict__ ctrG,
    const __half* __restrict__ Bw,
    const float* __restrict__ rowE, const float* __restrict__ colU,
    const float* __restrict__ rowD, const float* __restrict__ colB3,
    float* __restrict__ C, int M)
{
    extern __shared__ uint32_t s[];
    const int tid = threadIdx.x;
    const uint64_t pl = pol_evict_last();
    __shared__ int claim;

    // ---- Phase 1: SpMM rows ----
    for (;;) {
        if (tid == 0) claim = atomicAdd(ctrS, RCH);
        __syncthreads();
        const int r0 = claim;
        if (r0 >= M) { __syncthreads(); break; }
        const int rend = (r0 + RCH < M) ? r0 + RCH : M;
        for (int r = r0; r < rend; r++) {
            float2 acc = spmm_row_acc256(row_ptr, edge, in, r, tid, pl);
            __half2 h = __float22half2_rn(acc);
            *(__half2*)(A16 + (size_t)r * DD + (size_t)tid * 2) = h;
        }
        __threadfence();
        __syncthreads();
        if (tid < rend - r0) atomicExch((int*)&flags[r0 + tid], 1);
        __syncthreads();
    }

    // ---- Phase 2: GEMM tiles ----
    for (;;) {
        if (tid == 0) claim = atomicAdd(ctrG, 1);
        __syncthreads();
        const int t = claim;
        __syncthreads();
        if (t >= G1) break;
        const int bm = (t >> 2) * 128;
        if (tid < 128) {
            const int r = bm + tid;
            if (r < M) {
                while (flags[r] == 0) __nanosleep(64);
            }
        }
        __syncthreads();
        __threadfence();
        gemm_cta(t, s, A16, Bw, nullptr, rowE, colU, rowD, colB3,
                 C, nullptr, 1024, M);
        __syncthreads();
    }
}

// ---------------------------------------------------------------------------
// L1: W23 = W2@W3 || cnt/flags/counter zeroing
// ---------------------------------------------------------------------------
#define G512 (4 * DD)
__global__ void __launch_bounds__(128) gemm512cnt(
    const float* __restrict__ A, const float* __restrict__ B,
    float* __restrict__ C, int* __restrict__ cnt,
    int* __restrict__ flags, int* __restrict__ ctrS, int* __restrict__ ctrG,
    int M)
{
    const int bid = blockIdx.x;
    if (bid < G512) {
        const int n = (bid & 3) * 128 + threadIdx.x;
        const int k = bid >> 2;
        float acc = 0.f;
        #pragma unroll 8
        for (int j = 0; j < DD; j++)
            acc = fmaf(A[k * DD + j], B[j * DD + n], acc);
        C[k * DD + n] = acc;
    } else {
        int i = (bid - G512) * 128 + threadIdx.x;
        if (i < M) cnt[i] = 0;
        else if (i < 2 * M) flags[i - M] = 0;
        else if (i == 2 * M) *ctrS = 0;
        else if (i == 2 * M + 1) *ctrG = 0;
    }
}

// ---------------------------------------------------------------------------
// L2: prep (weight casts + A16 split) || hist
// ---------------------------------------------------------------------------
#define WN (3 * DD * DD)
__global__ void __launch_bounds__(256) prep_hist(
    const float* __restrict__ Lin1, const float* __restrict__ W1,
    const float* __restrict__ W23, const float* __restrict__ A1,
    __half* __restrict__ W16, __half* __restrict__ A16, int M,
    const int* __restrict__ rows, int* __restrict__ cnt, int E, int PB)
{
    const int bid = blockIdx.x;
    if (bid < PB) {
        size_t i = (size_t)bid * 256 + threadIdx.x;
        if (i < WN) {
            int w = (int)(i / (DD * DD));
            int j = (int)(i % (DD * DD));
            int n = j >> 9, k = j & 511;
            const float* src = (w == 0) ? Lin1 : (w == 1) ? W1 : W23;
            W16[i] = __float2half_rn(src[k * DD + n]);
            return;
        }
        size_t j = i - WN;
        if (j < (size_t)M * DD) {
            size_t r = j >> 9;
            int c = (int)(j & 511);
            A16[j] = __float2half_rn(A1[r * 513 + 1 + c]);
        }
    } else {
        int e = (bid - PB) * 256 + threadIdx.x;
        if (e < E) atomicAdd(&cnt[rows[e]], 1);
    }
}

// ---------------------------------------------------------------------------
// Host driver
// ---------------------------------------------------------------------------
extern "C" void kernel_launch(void* const* d_in, const int* in_sizes, int n_in,
                              void* d_out, int out_size)
{
    const float* A1       = (const float*)d_in[0];
    const int*   adj_rows = (const int*)  d_in[1];
    const int*   adj_cols = (const int*)  d_in[2];
    const float* adj_vals = (const float*)d_in[3];
    const float* Lin1     = (const float*)d_in[4];
    const float* Lin1_b   = (const float*)d_in[5];
    const float* nvec     = (const float*)d_in[6];
    const float* W1       = (const float*)d_in[7];
    const float* b1       = (const float*)d_in[8];
    const float* W2       = (const float*)d_in[9];
    const float* b2       = (const float*)d_in[10];
    const float* W3       = (const float*)d_in[11];
    const float* b3       = (const float*)d_in[12];
    float* out = (float*)d_out;

    const int M = in_sizes[6];   // 50000
    const int E = in_sizes[1];   // 1,600,000

    __half *A16, *H1, *H2, *W16;
    float *W23, *uvec, *dv, *ev;
    int *cnt, *rowptr, *cursor, *partial, *flags, *ctrS, *ctrG;
    int2 *edge;
    cudaGetSymbolAddress((void**)&A16, g_A16);
    cudaGetSymbolAddress((void**)&H1,  g_H1);
    cudaGetSymbolAddress((void**)&H2,  g_H2);
    cudaGetSymbolAddress((void**)&W16, g_W16);
    cudaGetSymbolAddress((void**)&W23,  g_W23);
    cudaGetSymbolAddress((void**)&uvec, g_uvec);
    cudaGetSymbolAddress((void**)&dv,   g_d);
    cudaGetSymbolAddress((void**)&ev,   g_e);
    cudaGetSymbolAddress((void**)&cnt,     g_cnt);
    cudaGetSymbolAddress((void**)&rowptr,  g_rowptr);
    cudaGetSymbolAddress((void**)&cursor,  g_cursor);
    cudaGetSymbolAddress((void**)&partial, g_partial);
    cudaGetSymbolAddress((void**)&edge,    g_edge);
    cudaGetSymbolAddress((void**)&flags,   g_flags);
    cudaGetSymbolAddress((void**)&ctrS,    g_ctrS);
    cudaGetSymbolAddress((void**)&ctrG,    g_ctrG);

    cudaFuncSetAttribute(fusedAB, cudaFuncAttributeMaxDynamicSharedMemorySize, GEMM_SMEM);
    cudaFuncSetAttribute(fusedE,  cudaFuncAttributeMaxDynamicSharedMemorySize, GEMM_SMEM);

    __half* Wp[3] = {W16, W16 + (size_t)DD * DD, W16 + (size_t)2 * DD * DD};

    const int eblk = (E + 255) / 256;
    const int zb   = (2 * M + 2 + 127) / 128;
    const size_t prep_total = (size_t)WN + (size_t)M * DD;
    const int PB = (int)((prep_total + 255) / 256);
    const int rsB = (M + 3) / 4;
    const int scanB = (M + SCB - 1) / SCB;

    // L1: W23 = W2@W3 || zero cnt/flags/counters
    gemm512cnt<<<G512 + zb, 128>>>(W2, W3, W23, cnt, flags, ctrS, ctrG, M);
    // L2: weight/input casts || hist
    prep_hist<<<PB + eblk, 256>>>(Lin1, W1, W23, A1, W16, A16, M,
                                  adj_rows, cnt, E, PB);
    // L3-4: parallel scan (top scan inlined into scan_add2)
    scan_part<<<scanB, SCB>>>(cnt, rowptr, partial, M);
    scan_add2<<<scanB, SCB>>>(rowptr, cursor, partial, M, E, scanB);
    // L5: a0 GEMM + H1 GEMM || scatter
    fusedAB<<<2 * G1 + eblk, 256, GEMM_SMEM>>>(A16, Wp[0], Wp[1], Lin1_b, b1,
                                               out + 512, H1, M,
                                               adj_rows, adj_cols, adj_vals,
                                               cursor, edge, E);
    // L6: spmm_mix || rowsum_d
    fusedC<<<M + rsB, 128>>>(rowptr, edge, H1, out + 512, nvec, H2, dv, M);
    // L7: spmm #2 || spmv_e || uvec
    fusedD<<<M + rsB + 4, 128>>>(rowptr, edge, H2, H1, dv, ev, b2, W3, uvec, M);
    // L8: persistent spmm#3 + final GEMM pipeline
    fusedE<<<PERSIST_CTAS, 256, GEMM_SMEM>>>(rowptr, edge, H1, A16, flags,
                                             ctrS, ctrG, Wp[2],
                                             ev, uvec, dv, b3, out, M);
}

// round 15
// speedup vs baseline: 1.3243x; 1.3243x over previous
#include <cuda_runtime.h>
#include <cuda_fp16.h>
#include <cstdint>
#include <cstddef>

#define NN 50000
#define EE 1600000
#define DD 512

// ---------------------------------------------------------------------------
// Device scratch (no runtime alloc allowed)
// ---------------------------------------------------------------------------
__device__ __half g_A16[(size_t)NN * DD];
__device__ __half g_H1[(size_t)NN * DD];
__device__ __half g_H2[(size_t)NN * DD];
__device__ __half g_W16[(size_t)3 * DD * DD];
__device__ float  g_W23[(size_t)DD * DD];
__device__ float  g_uvec[DD];
// CSR scratch
__device__ int   g_cnt[NN];
__device__ int   g_rowptr[NN + 1];
__device__ int   g_cursor[NN];
__device__ int   g_partial[256];
__device__ int2  g_edge[EE];
__device__ float g_d[NN];
__device__ float g_e[NN];

// ---------------------------------------------------------------------------
// Helpers
// ---------------------------------------------------------------------------
__device__ __forceinline__ uint32_t smem_to_u32(const void* p) {
    uint32_t a;
    asm("{ .reg .u64 t; cvta.to.shared.u64 t, %1; cvt.u32.u64 %0, t; }" : "=r"(a) : "l"(p));
    return a;
}

__device__ __forceinline__ void cp16(uint32_t dst, const void* src, bool valid) {
    int sz = valid ? 16 : 0;
    asm volatile("cp.async.cg.shared.global [%0], [%1], 16, %2;"
                 :: "r"(dst), "l"(src), "r"(sz) : "memory");
}
#define CP_COMMIT() asm volatile("cp.async.commit_group;" ::: "memory")
#define CP_WAIT(n)  asm volatile("cp.async.wait_group %0;" :: "n"(n) : "memory")

__device__ __forceinline__ void mma_f16(float* d, const uint32_t* a, const uint32_t* b) {
    asm volatile("mma.sync.aligned.m16n8k16.row.col.f32.f16.f16.f32 "
                 "{%0,%1,%2,%3}, {%4,%5,%6,%7}, {%8,%9}, {%0,%1,%2,%3};"
                 : "+f"(d[0]), "+f"(d[1]), "+f"(d[2]), "+f"(d[3])
                 : "r"(a[0]), "r"(a[1]), "r"(a[2]), "r"(a[3]), "r"(b[0]), "r"(b[1]));
}

__device__ __forceinline__ void ldsm_x4(uint32_t* r, uint32_t addr) {
    asm volatile("ldmatrix.sync.aligned.m8n8.x4.shared.b16 {%0,%1,%2,%3}, [%4];"
                 : "=r"(r[0]), "=r"(r[1]), "=r"(r[2]), "=r"(r[3]) : "r"(addr));
}
__device__ __forceinline__ void ldsm_x2(uint32_t* r, uint32_t addr) {
    asm volatile("ldmatrix.sync.aligned.m8n8.x2.shared.b16 {%0,%1}, [%2];"
                 : "=r"(r[0]), "=r"(r[1]) : "r"(addr));
}

// L2 cache policies via createpolicy (portable cache_hint form, any width)
__device__ __forceinline__ uint64_t pol_evict_last() {
    uint64_t p;
    asm("createpolicy.fractional.L2::evict_last.b64 %0, 1.0;" : "=l"(p));
    return p;
}
__device__ __forceinline__ uint64_t pol_evict_first() {
    uint64_t p;
    asm("createpolicy.fractional.L2::evict_first.b64 %0, 1.0;" : "=l"(p));
    return p;
}

__device__ __forceinline__ uint2 ldg_gather(const __half* p, uint64_t pol) {
    uint2 v;
    asm volatile("ld.global.nc.L2::cache_hint.v2.u32 {%0,%1}, [%2], %3;"
                 : "=r"(v.x), "=r"(v.y) : "l"(p), "l"(pol));
    return v;
}
__device__ __forceinline__ float4 ldg_once_f4(const float* p, uint64_t pol) {
    float4 v;
    asm volatile("ld.global.L2::cache_hint.v4.f32 {%0,%1,%2,%3}, [%4], %5;"
                 : "=f"(v.x), "=f"(v.y), "=f"(v.z), "=f"(v.w) : "l"(p), "l"(pol));
    return v;
}
__device__ __forceinline__ void stg_resident(__half* p, uint2 v, uint64_t pol) {
    asm volatile("st.global.L2::cache_hint.v2.u32 [%0], {%1,%2}, %3;"
                 :: "l"(p), "r"(v.x), "r"(v.y), "l"(pol) : "memory");
}
__device__ __forceinline__ void stg_resident32(__half* p, uint32_t v, uint64_t pol) {
    asm volatile("st.global.L2::cache_hint.u32 [%0], %1, %2;"
                 :: "l"(p), "r"(v), "l"(pol) : "memory");
}

// ---------------------------------------------------------------------------
// GEMM CTA body (ldmatrix + fp16 mma, fp32 accum)
// ---------------------------------------------------------------------------
#define BK 32
#define RSTRIDE 20
#define TILE_WORDS (128 * RSTRIDE)
#define STAGE_WORDS (2 * TILE_WORDS)
#define GEMM_SMEM (2 * STAGE_WORDS * 4)   // 40960 bytes
#define NBY ((NN + 127) / 128)            // 391
#define G1  (4 * NBY)                     // CTAs per N=512 GEMM: 1564

__device__ __forceinline__ void gemm_load_stage(
    uint32_t sbase, int stage, const __half* A, const __half* B,
    int bm, int bn, int kc, int M, int tid)
{
    const uint32_t st = sbase + (uint32_t)stage * STAGE_WORDS * 4;
    const int r0 = tid >> 2;
    const int r1 = r0 + 64;
    const int j  = tid & 3;
    const uint32_t d0 = st + (uint32_t)(r0 * RSTRIDE + j * 4) * 4;
    const uint32_t d1 = st + (uint32_t)(r1 * RSTRIDE + j * 4) * 4;
    const size_t koff = (size_t)kc * BK + j * 8;
    const bool v0 = (bm + r0) < M;
    const bool v1 = (bm + r1) < M;

    cp16(d0,                  A + (size_t)(bm + r0) * DD + koff, v0);
    cp16(d1,                  A + (size_t)(bm + r1) * DD + koff, v1);
    cp16(d0 + TILE_WORDS * 4, B + (size_t)(bn + r0) * DD + koff, true);
    cp16(d1 + TILE_WORDS * 4, B + (size_t)(bn + r1) * DD + koff, true);
}

__device__ void gemm_cta(
    int g, uint32_t* s,
    const __half* __restrict__ A, const __half* __restrict__ B,
    const float* __restrict__ bias,
    const float* __restrict__ rowE, const float* __restrict__ colU,
    const float* __restrict__ rowD, const float* __restrict__ colB3,
    float* __restrict__ C, __half* __restrict__ C16, int ldc, int M)
{
    const uint32_t sbase = smem_to_u32(s);
    const int tid  = threadIdx.x;
    const int warp = tid >> 5;
    const int lane = tid & 31;
    const int wm   = (warp & 1) * 64;
    const int wn   = (warp >> 1) * 32;
    const int grp  = lane >> 2;
    const int qd   = lane & 3;
    const int bm = (g >> 2) * 128;
    const int n0 = (g & 3) * 128;

    const int arow = wm + (lane & 15);
    const int acol = (lane >> 4) * 4;
    const int brow = wn + (lane & 7);
    const int bcol = ((lane >> 3) & 1) * 4;

    float acc[4][4][4];
    #pragma unroll
    for (int i = 0; i < 4; i++)
        #pragma unroll
        for (int j = 0; j < 4; j++)
            #pragma unroll
            for (int q = 0; q < 4; q++) acc[i][j][q] = 0.f;

    gemm_load_stage(sbase, 0, A, B, bm, n0, 0, M, tid);
    CP_COMMIT();

    #pragma unroll 1
    for (int kc = 0; kc < DD / BK; kc++) {
        if (kc + 1 < DD / BK) {
            gemm_load_stage(sbase, (kc + 1) & 1, A, B, bm, n0, kc + 1, M, tid);
            CP_COMMIT();
            CP_WAIT(1);
        } else {
            CP_WAIT(0);
        }
        __syncthreads();

        const uint32_t As_b = sbase + (uint32_t)(kc & 1) * STAGE_WORDS * 4;
        const uint32_t Bs_b = As_b + TILE_WORDS * 4;

        #pragma unroll
        for (int ks = 0; ks < 2; ks++) {
            const int kw = ks * 8;
            uint32_t ah[4][4];
            #pragma unroll
            for (int mi = 0; mi < 4; mi++)
                ldsm_x4(ah[mi], As_b + (uint32_t)((arow + mi * 16) * RSTRIDE + kw + acol) * 4);
            #pragma unroll
            for (int nj = 0; nj < 4; nj++) {
                uint32_t bh[2];
                ldsm_x2(bh, Bs_b + (uint32_t)((brow + nj * 8) * RSTRIDE + kw + bcol) * 4);
                #pragma unroll
                for (int mi = 0; mi < 4; mi++)
                    mma_f16(acc[mi][nj], ah[mi], bh);
            }
        }
        __syncthreads();
    }

    const uint64_t pl = pol_evict_last();
    #pragma unroll
    for (int mi = 0; mi < 4; mi++) {
        const int gr = bm + wm + mi * 16 + grp;
        float e0 = 0.f, d0v = 0.f, e1 = 0.f, d1v = 0.f;
        if (rowE) {
            if (gr < M)     { e0 = rowE[gr];     d0v = rowD[gr]; }
            if (gr + 8 < M) { e1 = rowE[gr + 8]; d1v = rowD[gr + 8]; }
        }
        #pragma unroll
        for (int nj = 0; nj < 4; nj++) {
            const int gc = n0 + wn + nj * 8 + qd * 2;
            float2 add0, add1;
            if (rowE) {
                const float2 uu = *(const float2*)(colU + gc);
                const float2 b3 = *(const float2*)(colB3 + gc);
                add0 = make_float2(e0 * uu.x + d0v * b3.x, e0 * uu.y + d0v * b3.y);
                add1 = make_float2(e1 * uu.x + d1v * b3.x, e1 * uu.y + d1v * b3.y);
            } else {
                const float2 bz = *(const float2*)(bias + gc);
                add0 = bz; add1 = bz;
            }
            float2 o0 = {acc[mi][nj][0] + add0.x, acc[mi][nj][1] + add0.y};
            float2 o1 = {acc[mi][nj][2] + add1.x, acc[mi][nj][3] + add1.y};
            if (C16) {
                __half2 h0 = __float22half2_rn(o0);
                __half2 h1 = __float22half2_rn(o1);
                if (gr < M)
                    stg_resident32(C16 + (size_t)gr * ldc + gc, *(uint32_t*)&h0, pl);
                if (gr + 8 < M)
                    stg_resident32(C16 + (size_t)(gr + 8) * ldc + gc, *(uint32_t*)&h1, pl);
            } else {
                if (gr < M)     *(float2*)(C + (size_t)gr * ldc + gc) = o0;
                if (gr + 8 < M) *(float2*)(C + (size_t)(gr + 8) * ldc + gc) = o1;
            }
        }
    }
}

// ---------------------------------------------------------------------------
// fusedAB: a0-GEMM CTAs + H1-GEMM CTAs + scatter CTAs in one grid
// ---------------------------------------------------------------------------
__global__ void __launch_bounds__(256, 2) fusedAB(
    const __half* __restrict__ A, const __half* __restrict__ B0,
    const __half* __restrict__ B1,
    const float* __restrict__ bias0, const float* __restrict__ bias1,
    float* __restrict__ C, __half* __restrict__ H1, int M,
    const int* __restrict__ rows, const int* __restrict__ cols,
    const float* __restrict__ vals, int* __restrict__ cursor,
    int2* __restrict__ edge, int E)
{
    extern __shared__ uint32_t s[];
    const int bid = blockIdx.x;
    if (bid < G1) {
        gemm_cta(bid, s, A, B0, bias0,
                 nullptr, nullptr, nullptr, nullptr, C, nullptr, 1024, M);
    } else if (bid < 2 * G1) {
        gemm_cta(bid - G1, s, A, B1, bias1,
                 nullptr, nullptr, nullptr, nullptr, nullptr, H1, DD, M);
    } else {
        int e = (bid - 2 * G1) * 256 + threadIdx.x;
        if (e < E) {
            int r = rows[e];
            int p = atomicAdd(&cursor[r], 1);
            edge[p] = make_int2(cols[e], __float_as_int(vals[e]));
        }
    }
}

// Final GEMM (standalone, rank-1 epilogue)
__global__ void __launch_bounds__(256, 2) gemm_final(
    const __half* __restrict__ A, const __half* __restrict__ B,
    const float* __restrict__ rowE, const float* __restrict__ colU,
    const float* __restrict__ rowD, const float* __restrict__ colB3,
    float* __restrict__ C, int M)
{
    extern __shared__ uint32_t s[];
    gemm_cta(blockIdx.x, s, A, B, nullptr, rowE, colU, rowD, colB3,
             C, nullptr, 1024, M);
}

// ---------------------------------------------------------------------------
// Parallel scan: scan_part + scan_add2 (top scan inlined per block)
// ---------------------------------------------------------------------------
#define SCB 256

__global__ void __launch_bounds__(SCB) scan_part(
    const int* __restrict__ cnt, int* __restrict__ row_ptr,
    int* __restrict__ partial, int M)
{
    __shared__ int sm[SCB];
    const int tid = threadIdx.x;
    const int i = blockIdx.x * SCB + tid;
    int v = (i < M) ? cnt[i] : 0;
    sm[tid] = v;
    __syncthreads();
    #pragma unroll
    for (int off = 1; off < SCB; off <<= 1) {
        int t = (tid >= off) ? sm[tid - off] : 0;
        __syncthreads();
        sm[tid] += t;
        __syncthreads();
    }
    if (i < M) row_ptr[i] = sm[tid] - v;
    if (tid == SCB - 1) partial[blockIdx.x] = sm[tid];
}

__global__ void __launch_bounds__(SCB) scan_add2(
    int* __restrict__ row_ptr, int* __restrict__ cursor,
    const int* __restrict__ partial, int M, int E, int nblk)
{
    __shared__ int sm[SCB];
    __shared__ int ex[SCB];
    const int tid = threadIdx.x;
    int v = (tid < nblk) ? partial[tid] : 0;
    sm[tid] = v;
    __syncthreads();
    #pragma unroll
    for (int off = 1; off < SCB; off <<= 1) {
        int t = (tid >= off) ? sm[tid - off] : 0;
        __syncthreads();
        sm[tid] += t;
        __syncthreads();
    }
    ex[tid] = sm[tid] - v;
    __syncthreads();
    const int off_b = ex[blockIdx.x];
    const int i = blockIdx.x * SCB + tid;
    if (i < M) {
        int val = row_ptr[i] + off_b;
        row_ptr[i] = val;
        cursor[i]  = val;
    }
    if (i == 0) row_ptr[M] = E;
}

// ---------------------------------------------------------------------------
// fp16 CSR SpMM core: 4-edge unrolled, evict_last gathers, fp32 accum
// ---------------------------------------------------------------------------
__device__ __forceinline__ void fma_h4(float4& acc, float v, uint2 r) {
    const float2 a0 = __half22float2(*(const __half2*)&r.x);
    const float2 a1 = __half22float2(*(const __half2*)&r.y);
    acc.x = fmaf(v, a0.x, acc.x); acc.y = fmaf(v, a0.y, acc.y);
    acc.z = fmaf(v, a1.x, acc.z); acc.w = fmaf(v, a1.y, acc.w);
}

__device__ __forceinline__ float4 spmm_row_acc_h(
    const int* __restrict__ row_ptr, const int2* __restrict__ edge,
    const __half* __restrict__ in, int r, int tid, uint64_t pol)
{
    const size_t off = (size_t)tid * 4;
    int e = row_ptr[r];
    const int end = row_ptr[r + 1];
    float4 acc = {0.f, 0.f, 0.f, 0.f};

    for (; e + 4 <= end; e += 4) {
        const int2 E0 = __ldg(edge + e);
        const int2 E1 = __ldg(edge + e + 1);
        const int2 E2 = __ldg(edge + e + 2);
        const int2 E3 = __ldg(edge + e + 3);
        const uint2 R0 = ldg_gather(in + (size_t)E0.x * DD + off, pol);
        const uint2 R1 = ldg_gather(in + (size_t)E1.x * DD + off, pol);
        const uint2 R2 = ldg_gather(in + (size_t)E2.x * DD + off, pol);
        const uint2 R3 = ldg_gather(in + (size_t)E3.x * DD + off, pol);
        fma_h4(acc, __int_as_float(E0.y), R0);
        fma_h4(acc, __int_as_float(E1.y), R1);
        fma_h4(acc, __int_as_float(E2.y), R2);
        fma_h4(acc, __int_as_float(E3.y), R3);
    }
    for (; e < end; e++) {
        const int2 E0 = __ldg(edge + e);
        const uint2 R0 = ldg_gather(in + (size_t)E0.x * DD + off, pol);
        fma_h4(acc, __int_as_float(E0.y), R0);
    }
    return acc;
}

__device__ __forceinline__ uint2 pack_h4(float4 v) {
    uint2 o;
    *(__half2*)&o.x = __float22half2_rn(make_float2(v.x, v.y));
    *(__half2*)&o.y = __float22half2_rn(make_float2(v.z, v.w));
    return o;
}

// fusedC: spmm_mix || rowsum_d
__global__ void __launch_bounds__(128) fusedC(
    const int* __restrict__ row_ptr, const int2* __restrict__ edge,
    const __half* __restrict__ in,
    const float* __restrict__ a0, const float* __restrict__ nvec,
    __half* __restrict__ x1, float* __restrict__ dvec, int M)
{
    const int bid = blockIdx.x;
    const int tid = threadIdx.x;
    if (bid < M) {
        const uint64_t pl = pol_evict_last();
        const uint64_t pf = pol_evict_first();
        float4 acc = spmm_row_acc_h(row_ptr, edge, in, bid, tid, pl);
        const float nv = nvec[bid];
        const float om = 1.f - nv;
        const float4 a = ldg_once_f4(a0 + (size_t)bid * 1024 + (size_t)tid * 4, pf);
        float4 o;
        o.x = a.x * nv + acc.x * om;
        o.y = a.y * nv + acc.y * om;
        o.z = a.z * nv + acc.z * om;
        o.w = a.w * nv + acc.w * om;
        stg_resident(x1 + (size_t)bid * DD + (size_t)tid * 4, pack_h4(o), pl);
    } else {
        const int r = (bid - M) * 4 + (tid >> 5);
        if (r >= M) return;
        const int lane = tid & 31;
        float acc = 0.f;
        for (int e = row_ptr[r] + lane; e < row_ptr[r + 1]; e += 32)
            acc += __int_as_float(__ldg(&edge[e].y));
        #pragma unroll
        for (int o = 16; o; o >>= 1) acc += __shfl_down_sync(0xffffffffu, acc, o);
        if (lane == 0) dvec[r] = acc;
    }
}

// fusedD: spmm (H1 = S·H2) || spmv_e || uvec
__global__ void __launch_bounds__(128) fusedD(
    const int* __restrict__ row_ptr, const int2* __restrict__ edge,
    const __half* __restrict__ in, __half* __restrict__ out,
    const float* __restrict__ dvec, float* __restrict__ evec,
    const float* __restrict__ b2, const float* __restrict__ W3,
    float* __restrict__ u, int M)
{
    const int bid = blockIdx.x;
    const int tid = threadIdx.x;
    const int UB = M + (M + 3) / 4;
    if (bid < M) {
        const uint64_t pl = pol_evict_last();
        float4 acc = spmm_row_acc_h(row_ptr, edge, in, bid, tid, pl);
        stg_resident(out + (size_t)bid * DD + (size_t)tid * 4, pack_h4(acc), pl);
    } else if (bid < UB) {
        const int r = (bid - M) * 4 + (tid >> 5);
        if (r >= M) return;
        const int lane = tid & 31;
        float acc = 0.f;
        for (int e = row_ptr[r] + lane; e < row_ptr[r + 1]; e += 32) {
            const int2 ev2 = __ldg(edge + e);
            acc = fmaf(__int_as_float(ev2.y), dvec[ev2.x], acc);
        }
        #pragma unroll
        for (int o = 16; o; o >>= 1) acc += __shfl_down_sync(0xffffffffu, acc, o);
        if (lane == 0) evec[r] = acc;
    } else {
        const int n = (bid - UB) * 128 + tid;
        float acc = 0.f;
        #pragma unroll 8
        for (int j = 0; j < DD; j++)
            acc = fmaf(b2[j], W3[j * DD + n], acc);
        u[n] = acc;
    }
}

// Plain fp16 SpMM (#3)
__global__ void __launch_bounds__(128) spmm_csr_h(
    const int* __restrict__ row_ptr, const int2* __restrict__ edge,
    const __half* __restrict__ in, __half* __restrict__ out)
{
    const uint64_t pl = pol_evict_last();
    float4 acc = spmm_row_acc_h(row_ptr, edge, in, blockIdx.x, threadIdx.x, pl);
    uint2 o = pack_h4(acc);
    *(uint2*)(out + (size_t)blockIdx.x * DD + (size_t)threadIdx.x * 4) = o;
}

// ---------------------------------------------------------------------------
// L1: W23 = W2@W3 || cnt zeroing
// ---------------------------------------------------------------------------
#define G512 (4 * DD)
__global__ void __launch_bounds__(128) gemm512cnt(
    const float* __restrict__ A, const float* __restrict__ B,
    float* __restrict__ C, int* __restrict__ cnt, int M)
{
    const int bid = blockIdx.x;
    if (bid < G512) {
        const int n = (bid & 3) * 128 + threadIdx.x;
        const int k = bid >> 2;
        float acc = 0.f;
        #pragma unroll 8
        for (int j = 0; j < DD; j++)
            acc = fmaf(A[k * DD + j], B[j * DD + n], acc);
        C[k * DD + n] = acc;
    } else {
        int i = (bid - G512) * 128 + threadIdx.x;
        if (i < M) cnt[i] = 0;
    }
}

// ---------------------------------------------------------------------------
// L2: prep (weight casts + A16 split) || hist
// ---------------------------------------------------------------------------
#define WN (3 * DD * DD)
__global__ void __launch_bounds__(256) prep_hist(
    const float* __restrict__ Lin1, const float* __restrict__ W1,
    const float* __restrict__ W23, const float* __restrict__ A1,
    __half* __restrict__ W16, __half* __restrict__ A16, int M,
    const int* __restrict__ rows, int* __restrict__ cnt, int E, int PB)
{
    const int bid = blockIdx.x;
    if (bid < PB) {
        size_t i = (size_t)bid * 256 + threadIdx.x;
        if (i < WN) {
            int w = (int)(i / (DD * DD));
            int j = (int)(i % (DD * DD));
            int n = j >> 9, k = j & 511;
            const float* src = (w == 0) ? Lin1 : (w == 1) ? W1 : W23;
            W16[i] = __float2half_rn(src[k * DD + n]);
            return;
        }
        size_t j = i - WN;
        if (j < (size_t)M * DD) {
            size_t r = j >> 9;
            int c = (int)(j & 511);
            A16[j] = __float2half_rn(A1[r * 513 + 1 + c]);
        }
    } else {
        int e = (bid - PB) * 256 + threadIdx.x;
        if (e < E) atomicAdd(&cnt[rows[e]], 1);
    }
}

// ---------------------------------------------------------------------------
// Host driver
// ---------------------------------------------------------------------------
extern "C" void kernel_launch(void* const* d_in, const int* in_sizes, int n_in,
                              void* d_out, int out_size)
{
    const float* A1       = (const float*)d_in[0];
    const int*   adj_rows = (const int*)  d_in[1];
    const int*   adj_cols = (const int*)  d_in[2];
    const float* adj_vals = (const float*)d_in[3];
    const float* Lin1     = (const float*)d_in[4];
    const float* Lin1_b   = (const float*)d_in[5];
    const float* nvec     = (const float*)d_in[6];
    const float* W1       = (const float*)d_in[7];
    const float* b1       = (const float*)d_in[8];
    const float* W2       = (const float*)d_in[9];
    const float* b2       = (const float*)d_in[10];
    const float* W3       = (const float*)d_in[11];
    const float* b3       = (const float*)d_in[12];
    float* out = (float*)d_out;

    const int M = in_sizes[6];   // 50000
    const int E = in_sizes[1];   // 1,600,000

    __half *A16, *H1, *H2, *W16;
    float *W23, *uvec, *dv, *ev;
    int *cnt, *rowptr, *cursor, *partial;
    int2 *edge;
    cudaGetSymbolAddress((void**)&A16, g_A16);
    cudaGetSymbolAddress((void**)&H1,  g_H1);
    cudaGetSymbolAddress((void**)&H2,  g_H2);
    cudaGetSymbolAddress((void**)&W16, g_W16);
    cudaGetSymbolAddress((void**)&W23,  g_W23);
    cudaGetSymbolAddress((void**)&uvec, g_uvec);
    cudaGetSymbolAddress((void**)&dv,   g_d);
    cudaGetSymbolAddress((void**)&ev,   g_e);
    cudaGetSymbolAddress((void**)&cnt,     g_cnt);
    cudaGetSymbolAddress((void**)&rowptr,  g_rowptr);
    cudaGetSymbolAddress((void**)&cursor,  g_cursor);
    cudaGetSymbolAddress((void**)&partial, g_partial);
    cudaGetSymbolAddress((void**)&edge,    g_edge);

    cudaFuncSetAttribute(fusedAB,    cudaFuncAttributeMaxDynamicSharedMemorySize, GEMM_SMEM);
    cudaFuncSetAttribute(gemm_final, cudaFuncAttributeMaxDynamicSharedMemorySize, GEMM_SMEM);

    __half* Wp[3] = {W16, W16 + (size_t)DD * DD, W16 + (size_t)2 * DD * DD};

    const int eblk = (E + 255) / 256;
    const int cntB = (M + 127) / 128;
    const size_t prep_total = (size_t)WN + (size_t)M * DD;
    const int PB = (int)((prep_total + 255) / 256);
    const int rsB = (M + 3) / 4;
    const int scanB = (M + SCB - 1) / SCB;

    // L1: W23 = W2@W3 || cnt zero
    gemm512cnt<<<G512 + cntB, 128>>>(W2, W3, W23, cnt, M);
    // L2: weight/input casts || hist
    prep_hist<<<PB + eblk, 256>>>(Lin1, W1, W23, A1, W16, A16, M,
                                  adj_rows, cnt, E, PB);
    // L3-4: parallel scan (top scan inlined into scan_add2)
    scan_part<<<scanB, SCB>>>(cnt, rowptr, partial, M);
    scan_add2<<<scanB, SCB>>>(rowptr, cursor, partial, M, E, scanB);
    // L5: a0 GEMM + H1 GEMM || scatter
    fusedAB<<<2 * G1 + eblk, 256, GEMM_SMEM>>>(A16, Wp[0], Wp[1], Lin1_b, b1,
                                               out + 512, H1, M,
                                               adj_rows, adj_cols, adj_vals,
                                               cursor, edge, E);
    // L6: spmm_mix || rowsum_d
    fusedC<<<M + rsB, 128>>>(rowptr, edge, H1, out + 512, nvec, H2, dv, M);
    // L7: spmm #2 || spmv_e || uvec
    fusedD<<<M + rsB + 4, 128>>>(rowptr, edge, H2, H1, dv, ev, b2, W3, uvec, M);
    // L8: spmm #3
    spmm_csr_h<<<M, 128>>>(rowptr, edge, H1, A16);
    // L9: final GEMM: out[:,0:512) = t2 @ W23 + e⊗u + d⊗b3
    gemm_final<<<G1, 256, GEMM_SMEM>>>(A16, Wp[2], ev, uvec, dv, b3, out, M);
}

// round 16
// speedup vs baseline: 1.3892x; 1.0490x over previous
#include <cuda_runtime.h>
#include <cuda_fp16.h>
#include <cstdint>
#include <cstddef>

#define NN 50000
#define EE 1600000
#define DD 512

// ---------------------------------------------------------------------------
// Device scratch (no runtime alloc allowed)
// ---------------------------------------------------------------------------
__device__ __half g_A16[(size_t)NN * DD];
__device__ __half g_H1[(size_t)NN * DD];
__device__ __half g_H2[(size_t)NN * DD];   // also scratch for W2/W3^T fp16 casts
__device__ __half g_W16[(size_t)3 * DD * DD];
__device__ float  g_uvec[DD];
// CSR scratch
__device__ int   g_cnt[NN];
__device__ int   g_rowptr[NN + 1];
__device__ int   g_cursor[NN];
__device__ int   g_partial[256];
__device__ int2  g_edge[EE];
__device__ float g_d[NN];
__device__ float g_e[NN];

// ---------------------------------------------------------------------------
// Helpers
// ---------------------------------------------------------------------------
__device__ __forceinline__ uint32_t smem_to_u32(const void* p) {
    uint32_t a;
    asm("{ .reg .u64 t; cvta.to.shared.u64 t, %1; cvt.u32.u64 %0, t; }" : "=r"(a) : "l"(p));
    return a;
}

__device__ __forceinline__ void cp16(uint32_t dst, const void* src, bool valid) {
    int sz = valid ? 16 : 0;
    asm volatile("cp.async.cg.shared.global [%0], [%1], 16, %2;"
                 :: "r"(dst), "l"(src), "r"(sz) : "memory");
}
#define CP_COMMIT() asm volatile("cp.async.commit_group;" ::: "memory")
#define CP_WAIT(n)  asm volatile("cp.async.wait_group %0;" :: "n"(n) : "memory")

__device__ __forceinline__ void mma_f16(float* d, const uint32_t* a, const uint32_t* b) {
    asm volatile("mma.sync.aligned.m16n8k16.row.col.f32.f16.f16.f32 "
                 "{%0,%1,%2,%3}, {%4,%5,%6,%7}, {%8,%9}, {%0,%1,%2,%3};"
                 : "+f"(d[0]), "+f"(d[1]), "+f"(d[2]), "+f"(d[3])
                 : "r"(a[0]), "r"(a[1]), "r"(a[2]), "r"(a[3]), "r"(b[0]), "r"(b[1]));
}

__device__ __forceinline__ void ldsm_x4(uint32_t* r, uint32_t addr) {
    asm volatile("ldmatrix.sync.aligned.m8n8.x4.shared.b16 {%0,%1,%2,%3}, [%4];"
                 : "=r"(r[0]), "=r"(r[1]), "=r"(r[2]), "=r"(r[3]) : "r"(addr));
}
__device__ __forceinline__ void ldsm_x2(uint32_t* r, uint32_t addr) {
    asm volatile("ldmatrix.sync.aligned.m8n8.x2.shared.b16 {%0,%1}, [%2];"
                 : "=r"(r[0]), "=r"(r[1]) : "r"(addr));
}

// L2 cache policies via createpolicy
__device__ __forceinline__ uint64_t pol_evict_last() {
    uint64_t p;
    asm("createpolicy.fractional.L2::evict_last.b64 %0, 1.0;" : "=l"(p));
    return p;
}
__device__ __forceinline__ uint64_t pol_evict_first() {
    uint64_t p;
    asm("createpolicy.fractional.L2::evict_first.b64 %0, 1.0;" : "=l"(p));
    return p;
}

__device__ __forceinline__ uint2 ldg_gather(const __half* p, uint64_t pol) {
    uint2 v;
    asm volatile("ld.global.nc.L2::cache_hint.v2.u32 {%0,%1}, [%2], %3;"
                 : "=r"(v.x), "=r"(v.y) : "l"(p), "l"(pol));
    return v;
}
__device__ __forceinline__ float4 ldg_once_f4(const float* p, uint64_t pol) {
    float4 v;
    asm volatile("ld.global.L2::cache_hint.v4.f32 {%0,%1,%2,%3}, [%4], %5;"
                 : "=f"(v.x), "=f"(v.y), "=f"(v.z), "=f"(v.w) : "l"(p), "l"(pol));
    return v;
}
__device__ __forceinline__ void stg_resident(__half* p, uint2 v, uint64_t pol) {
    asm volatile("st.global.L2::cache_hint.v2.u32 [%0], {%1,%2}, %3;"
                 :: "l"(p), "r"(v.x), "r"(v.y), "l"(pol) : "memory");
}
__device__ __forceinline__ void stg_resident32(__half* p, uint32_t v, uint64_t pol) {
    asm volatile("st.global.L2::cache_hint.u32 [%0], %1, %2;"
                 :: "l"(p), "r"(v), "l"(pol) : "memory");
}

// ---------------------------------------------------------------------------
// GEMM CTA body (ldmatrix + fp16 mma, fp32 accum)
// Epilogue modes: rowE != null -> rank-1 corrections; else bias != null ->
// bias add; else zero add (used by the W23^T weight-product tiles).
// ---------------------------------------------------------------------------
#define BK 32
#define RSTRIDE 20
#define TILE_WORDS (128 * RSTRIDE)
#define STAGE_WORDS (2 * TILE_WORDS)
#define GEMM_SMEM (2 * STAGE_WORDS * 4)   // 40960 bytes
#define NBY ((NN + 127) / 128)            // 391
#define G1  (4 * NBY)                     // CTAs per N=512 GEMM: 1564

__device__ __forceinline__ void gemm_load_stage(
    uint32_t sbase, int stage, const __half* A, const __half* B,
    int bm, int bn, int kc, int M, int tid)
{
    const uint32_t st = sbase + (uint32_t)stage * STAGE_WORDS * 4;
    const int r0 = tid >> 2;
    const int r1 = r0 + 64;
    const int j  = tid & 3;
    const uint32_t d0 = st + (uint32_t)(r0 * RSTRIDE + j * 4) * 4;
    const uint32_t d1 = st + (uint32_t)(r1 * RSTRIDE + j * 4) * 4;
    const size_t koff = (size_t)kc * BK + j * 8;
    const bool v0 = (bm + r0) < M;
    const bool v1 = (bm + r1) < M;

    cp16(d0,                  A + (size_t)(bm + r0) * DD + koff, v0);
    cp16(d1,                  A + (size_t)(bm + r1) * DD + koff, v1);
    cp16(d0 + TILE_WORDS * 4, B + (size_t)(bn + r0) * DD + koff, true);
    cp16(d1 + TILE_WORDS * 4, B + (size_t)(bn + r1) * DD + koff, true);
}

__device__ void gemm_cta(
    int g, uint32_t* s,
    const __half* __restrict__ A, const __half* __restrict__ B,
    const float* __restrict__ bias,
    const float* __restrict__ rowE, const float* __restrict__ colU,
    const float* __restrict__ rowD, const float* __restrict__ colB3,
    float* __restrict__ C, __half* __restrict__ C16, int ldc, int M)
{
    const uint32_t sbase = smem_to_u32(s);
    const int tid  = threadIdx.x;
    const int warp = tid >> 5;
    const int lane = tid & 31;
    const int wm   = (warp & 1) * 64;
    const int wn   = (warp >> 1) * 32;
    const int grp  = lane >> 2;
    const int qd   = lane & 3;
    const int bm = (g >> 2) * 128;
    const int n0 = (g & 3) * 128;

    const int arow = wm + (lane & 15);
    const int acol = (lane >> 4) * 4;
    const int brow = wn + (lane & 7);
    const int bcol = ((lane >> 3) & 1) * 4;

    float acc[4][4][4];
    #pragma unroll
    for (int i = 0; i < 4; i++)
        #pragma unroll
        for (int j = 0; j < 4; j++)
            #pragma unroll
            for (int q = 0; q < 4; q++) acc[i][j][q] = 0.f;

    gemm_load_stage(sbase, 0, A, B, bm, n0, 0, M, tid);
    CP_COMMIT();

    #pragma unroll 1
    for (int kc = 0; kc < DD / BK; kc++) {
        if (kc + 1 < DD / BK) {
            gemm_load_stage(sbase, (kc + 1) & 1, A, B, bm, n0, kc + 1, M, tid);
            CP_COMMIT();
            CP_WAIT(1);
        } else {
            CP_WAIT(0);
        }
        __syncthreads();

        const uint32_t As_b = sbase + (uint32_t)(kc & 1) * STAGE_WORDS * 4;
        const uint32_t Bs_b = As_b + TILE_WORDS * 4;

        #pragma unroll
        for (int ks = 0; ks < 2; ks++) {
            const int kw = ks * 8;
            uint32_t ah[4][4];
            #pragma unroll
            for (int mi = 0; mi < 4; mi++)
                ldsm_x4(ah[mi], As_b + (uint32_t)((arow + mi * 16) * RSTRIDE + kw + acol) * 4);
            #pragma unroll
            for (int nj = 0; nj < 4; nj++) {
                uint32_t bh[2];
                ldsm_x2(bh, Bs_b + (uint32_t)((brow + nj * 8) * RSTRIDE + kw + bcol) * 4);
                #pragma unroll
                for (int mi = 0; mi < 4; mi++)
                    mma_f16(acc[mi][nj], ah[mi], bh);
            }
        }
        __syncthreads();
    }

    const uint64_t pl = pol_evict_last();
    #pragma unroll
    for (int mi = 0; mi < 4; mi++) {
        const int gr = bm + wm + mi * 16 + grp;
        float e0 = 0.f, d0v = 0.f, e1 = 0.f, d1v = 0.f;
        if (rowE) {
            if (gr < M)     { e0 = rowE[gr];     d0v = rowD[gr]; }
            if (gr + 8 < M) { e1 = rowE[gr + 8]; d1v = rowD[gr + 8]; }
        }
        #pragma unroll
        for (int nj = 0; nj < 4; nj++) {
            const int gc = n0 + wn + nj * 8 + qd * 2;
            float2 add0, add1;
            if (rowE) {
                const float2 uu = *(const float2*)(colU + gc);
                const float2 b3 = *(const float2*)(colB3 + gc);
                add0 = make_float2(e0 * uu.x + d0v * b3.x, e0 * uu.y + d0v * b3.y);
                add1 = make_float2(e1 * uu.x + d1v * b3.x, e1 * uu.y + d1v * b3.y);
            } else if (bias) {
                const float2 bz = *(const float2*)(bias + gc);
                add0 = bz; add1 = bz;
            } else {
                add0 = make_float2(0.f, 0.f);
                add1 = make_float2(0.f, 0.f);
            }
            float2 o0 = {acc[mi][nj][0] + add0.x, acc[mi][nj][1] + add0.y};
            float2 o1 = {acc[mi][nj][2] + add1.x, acc[mi][nj][3] + add1.y};
            if (C16) {
                __half2 h0 = __float22half2_rn(o0);
                __half2 h1 = __float22half2_rn(o1);
                if (gr < M)
                    stg_resident32(C16 + (size_t)gr * ldc + gc, *(uint32_t*)&h0, pl);
                if (gr + 8 < M)
                    stg_resident32(C16 + (size_t)(gr + 8) * ldc + gc, *(uint32_t*)&h1, pl);
            } else {
                if (gr < M)     *(float2*)(C + (size_t)gr * ldc + gc) = o0;
                if (gr + 8 < M) *(float2*)(C + (size_t)(gr + 8) * ldc + gc) = o1;
            }
        }
    }
}

// ---------------------------------------------------------------------------
// fusedAB: a0-GEMM + H1-GEMM + scatter + W23^T-product CTAs in one grid
// W23^T[n][k] = sum_j W3t[n][j] * W2c[k][j]  (A = W3t, B = W2c; fp16 out)
// ---------------------------------------------------------------------------
__global__ void __launch_bounds__(256, 2) fusedAB(
    const __half* __restrict__ A, const __half* __restrict__ B0,
    const __half* __restrict__ B1,
    const float* __restrict__ bias0, const float* __restrict__ bias1,
    float* __restrict__ C, __half* __restrict__ H1, int M,
    const int* __restrict__ rows, const int* __restrict__ cols,
    const float* __restrict__ vals, int* __restrict__ cursor,
    int2* __restrict__ edge, int E, int EB,
    const __half* __restrict__ W3t, const __half* __restrict__ W2c,
    __half* __restrict__ W23T)
{
    extern __shared__ uint32_t s[];
    const int bid = blockIdx.x;
    if (bid < G1) {
        gemm_cta(bid, s, A, B0, bias0,
                 nullptr, nullptr, nullptr, nullptr, C, nullptr, 1024, M);
    } else if (bid < 2 * G1) {
        gemm_cta(bid - G1, s, A, B1, bias1,
                 nullptr, nullptr, nullptr, nullptr, nullptr, H1, DD, M);
    } else if (bid < 2 * G1 + EB) {
        int e = (bid - 2 * G1) * 256 + threadIdx.x;
        if (e < E) {
            int r = rows[e];
            int p = atomicAdd(&cursor[r], 1);
            edge[p] = make_int2(cols[e], __float_as_int(vals[e]));
        }
    } else {
        // 16 CTAs: W23^T = W3^T @ W2^T via tensor cores (zero epilogue)
        gemm_cta(bid - 2 * G1 - EB, s, W3t, W2c, nullptr,
                 nullptr, nullptr, nullptr, nullptr, nullptr, W23T, DD, DD);
    }
}

// Final GEMM (standalone, rank-1 epilogue)
__global__ void __launch_bounds__(256, 2) gemm_final(
    const __half* __restrict__ A, const __half* __restrict__ B,
    const float* __restrict__ rowE, const float* __restrict__ colU,
    const float* __restrict__ rowD, const float* __restrict__ colB3,
    float* __restrict__ C, int M)
{
    extern __shared__ uint32_t s[];
    gemm_cta(blockIdx.x, s, A, B, nullptr, rowE, colU, rowD, colB3,
             C, nullptr, 1024, M);
}

// ---------------------------------------------------------------------------
// Parallel scan: scan_part + scan_add2
// ---------------------------------------------------------------------------
#define SCB 256

__global__ void __launch_bounds__(SCB) scan_part(
    const int* __restrict__ cnt, int* __restrict__ row_ptr,
    int* __restrict__ partial, int M)
{
    __shared__ int sm[SCB];
    const int tid = threadIdx.x;
    const int i = blockIdx.x * SCB + tid;
    int v = (i < M) ? cnt[i] : 0;
    sm[tid] = v;
    __syncthreads();
    #pragma unroll
    for (int off = 1; off < SCB; off <<= 1) {
        int t = (tid >= off) ? sm[tid - off] : 0;
        __syncthreads();
        sm[tid] += t;
        __syncthreads();
    }
    if (i < M) row_ptr[i] = sm[tid] - v;
    if (tid == SCB - 1) partial[blockIdx.x] = sm[tid];
}

__global__ void __launch_bounds__(SCB) scan_add2(
    int* __restrict__ row_ptr, int* __restrict__ cursor,
    const int* __restrict__ partial, int M, int E, int nblk)
{
    __shared__ int sm[SCB];
    __shared__ int ex[SCB];
    const int tid = threadIdx.x;
    int v = (tid < nblk) ? partial[tid] : 0;
    sm[tid] = v;
    __syncthreads();
    #pragma unroll
    for (int off = 1; off < SCB; off <<= 1) {
        int t = (tid >= off) ? sm[tid - off] : 0;
        __syncthreads();
        sm[tid] += t;
        __syncthreads();
    }
    ex[tid] = sm[tid] - v;
    __syncthreads();
    const int off_b = ex[blockIdx.x];
    const int i = blockIdx.x * SCB + tid;
    if (i < M) {
        int val = row_ptr[i] + off_b;
        row_ptr[i] = val;
        cursor[i]  = val;
    }
    if (i == 0) row_ptr[M] = E;
}

// ---------------------------------------------------------------------------
// fp16 CSR SpMM core: 4-edge unrolled, evict_last gathers, fp32 accum
// ---------------------------------------------------------------------------
__device__ __forceinline__ void fma_h4(float4& acc, float v, uint2 r) {
    const float2 a0 = __half22float2(*(const __half2*)&r.x);
    const float2 a1 = __half22float2(*(const __half2*)&r.y);
    acc.x = fmaf(v, a0.x, acc.x); acc.y = fmaf(v, a0.y, acc.y);
    acc.z = fmaf(v, a1.x, acc.z); acc.w = fmaf(v, a1.y, acc.w);
}

__device__ __forceinline__ float4 spmm_row_acc_h(
    const int* __restrict__ row_ptr, const int2* __restrict__ edge,
    const __half* __restrict__ in, int r, int tid, uint64_t pol)
{
    const size_t off = (size_t)tid * 4;
    int e = row_ptr[r];
    const int end = row_ptr[r + 1];
    float4 acc = {0.f, 0.f, 0.f, 0.f};

    for (; e + 4 <= end; e += 4) {
        const int2 E0 = __ldg(edge + e);
        const int2 E1 = __ldg(edge + e + 1);
        const int2 E2 = __ldg(edge + e + 2);
        const int2 E3 = __ldg(edge + e + 3);
        const uint2 R0 = ldg_gather(in + (size_t)E0.x * DD + off, pol);
        const uint2 R1 = ldg_gather(in + (size_t)E1.x * DD + off, pol);
        const uint2 R2 = ldg_gather(in + (size_t)E2.x * DD + off, pol);
        const uint2 R3 = ldg_gather(in + (size_t)E3.x * DD + off, pol);
        fma_h4(acc, __int_as_float(E0.y), R0);
        fma_h4(acc, __int_as_float(E1.y), R1);
        fma_h4(acc, __int_as_float(E2.y), R2);
        fma_h4(acc, __int_as_float(E3.y), R3);
    }
    for (; e < end; e++) {
        const int2 E0 = __ldg(edge + e);
        const uint2 R0 = ldg_gather(in + (size_t)E0.x * DD + off, pol);
        fma_h4(acc, __int_as_float(E0.y), R0);
    }
    return acc;
}

__device__ __forceinline__ uint2 pack_h4(float4 v) {
    uint2 o;
    *(__half2*)&o.x = __float22half2_rn(make_float2(v.x, v.y));
    *(__half2*)&o.y = __float22half2_rn(make_float2(v.z, v.w));
    return o;
}

// fusedC: spmm_mix || rowsum_d
__global__ void __launch_bounds__(128) fusedC(
    const int* __restrict__ row_ptr, const int2* __restrict__ edge,
    const __half* __restrict__ in,
    const float* __restrict__ a0, const float* __restrict__ nvec,
    __half* __restrict__ x1, float* __restrict__ dvec, int M)
{
    const int bid = blockIdx.x;
    const int tid = threadIdx.x;
    if (bid < M) {
        const uint64_t pl = pol_evict_last();
        const uint64_t pf = pol_evict_first();
        float4 acc = spmm_row_acc_h(row_ptr, edge, in, bid, tid, pl);
        const float nv = nvec[bid];
        const float om = 1.f - nv;
        const float4 a = ldg_once_f4(a0 + (size_t)bid * 1024 + (size_t)tid * 4, pf);
        float4 o;
        o.x = a.x * nv + acc.x * om;
        o.y = a.y * nv + acc.y * om;
        o.z = a.z * nv + acc.z * om;
        o.w = a.w * nv + acc.w * om;
        stg_resident(x1 + (size_t)bid * DD + (size_t)tid * 4, pack_h4(o), pl);
    } else {
        const int r = (bid - M) * 4 + (tid >> 5);
        if (r >= M) return;
        const int lane = tid & 31;
        float acc = 0.f;
        for (int e = row_ptr[r] + lane; e < row_ptr[r + 1]; e += 32)
            acc += __int_as_float(__ldg(&edge[e].y));
        #pragma unroll
        for (int o = 16; o; o >>= 1) acc += __shfl_down_sync(0xffffffffu, acc, o);
        if (lane == 0) dvec[r] = acc;
    }
}

// fusedD: spmm (H1 = S·H2) || spmv_e || uvec
__global__ void __launch_bounds__(128) fusedD(
    const int* __restrict__ row_ptr, const int2* __restrict__ edge,
    const __half* __restrict__ in, __half* __restrict__ out,
    const float* __restrict__ dvec, float* __restrict__ evec,
    const float* __restrict__ b2, const float* __restrict__ W3,
    float* __restrict__ u, int M)
{
    const int bid = blockIdx.x;
    const int tid = threadIdx.x;
    const int UB = M + (M + 3) / 4;
    if (bid < M) {
        const uint64_t pl = pol_evict_last();
        float4 acc = spmm_row_acc_h(row_ptr, edge, in, bid, tid, pl);
        stg_resident(out + (size_t)bid * DD + (size_t)tid * 4, pack_h4(acc), pl);
    } else if (bid < UB) {
        const int r = (bid - M) * 4 + (tid >> 5);
        if (r >= M) return;
        const int lane = tid & 31;
        float acc = 0.f;
        for (int e = row_ptr[r] + lane; e < row_ptr[r + 1]; e += 32) {
            const int2 ev2 = __ldg(edge + e);
            acc = fmaf(__int_as_float(ev2.y), dvec[ev2.x], acc);
        }
        #pragma unroll
        for (int o = 16; o; o >>= 1) acc += __shfl_down_sync(0xffffffffu, acc, o);
        if (lane == 0) evec[r] = acc;
    } else {
        const int n = (bid - UB) * 128 + tid;
        float acc = 0.f;
        #pragma unroll 8
        for (int j = 0; j < DD; j++)
            acc = fmaf(b2[j], W3[j * DD + n], acc);
        u[n] = acc;
    }
}

// Plain fp16 SpMM (#3)
__global__ void __launch_bounds__(128) spmm_csr_h(
    const int* __restrict__ row_ptr, const int2* __restrict__ edge,
    const __half* __restrict__ in, __half* __restrict__ out)
{
    const uint64_t pl = pol_evict_last();
    float4 acc = spmm_row_acc_h(row_ptr, edge, in, blockIdx.x, threadIdx.x, pl);
    uint2 o = pack_h4(acc);
    *(uint2*)(out + (size_t)blockIdx.x * DD + (size_t)threadIdx.x * 4) = o;
}

// ---------------------------------------------------------------------------
// L1: prep (4 weight casts + A16 split) || hist    (cnt zeroed by memset node)
//   w0: Wp[0] = Lin1^T   w1: Wp[1] = W1^T
//   w2: W2c   = W2 (plain)   w3: W3t = W3^T       (into H2 scratch)
// ---------------------------------------------------------------------------
#define WN4 (4 * DD * DD)
__global__ void __launch_bounds__(256) prep_hist(
    const float* __restrict__ Lin1, const float* __restrict__ W1,
    const float* __restrict__ W2,   const float* __restrict__ W3,
    const float* __restrict__ A1,
    __half* __restrict__ W16, __half* __restrict__ W2c,
    __half* __restrict__ W3t, __half* __restrict__ A16, int M,
    const int* __restrict__ rows, int* __restrict__ cnt, int E, int PB)
{
    const int bid = blockIdx.x;
    if (bid < PB) {
        size_t i = (size_t)bid * 256 + threadIdx.x;
        if (i < WN4) {
            int w = (int)(i / (DD * DD));
            int j = (int)(i % (DD * DD));
            int n = j >> 9, k = j & 511;
            if (w == 0)      W16[j]            = __float2half_rn(Lin1[k * DD + n]);
            else if (w == 1) W16[DD * DD + j]  = __float2half_rn(W1[k * DD + n]);
            else if (w == 2) W2c[j]            = __float2half_rn(W2[j]);
            else             W3t[j]            = __float2half_rn(W3[k * DD + n]);
            return;
        }
        size_t j = i - WN4;
        if (j < (size_t)M * DD) {
            size_t r = j >> 9;
            int c = (int)(j & 511);
            A16[j] = __float2half_rn(A1[r * 513 + 1 + c]);
        }
    } else {
        int e = (bid - PB) * 256 + threadIdx.x;
        if (e < E) atomicAdd(&cnt[rows[e]], 1);
    }
}

// ---------------------------------------------------------------------------
// Host driver
// ---------------------------------------------------------------------------
extern "C" void kernel_launch(void* const* d_in, const int* in_sizes, int n_in,
                              void* d_out, int out_size)
{
    const float* A1       = (const float*)d_in[0];
    const int*   adj_rows = (const int*)  d_in[1];
    const int*   adj_cols = (const int*)  d_in[2];
    const float* adj_vals = (const float*)d_in[3];
    const float* Lin1     = (const float*)d_in[4];
    const float* Lin1_b   = (const float*)d_in[5];
    const float* nvec     = (const float*)d_in[6];
    const float* W1       = (const float*)d_in[7];
    const float* b1       = (const float*)d_in[8];
    const float* W2       = (const float*)d_in[9];
    const float* b2       = (const float*)d_in[10];
    const float* W3       = (const float*)d_in[11];
    const float* b3       = (const float*)d_in[12];
    float* out = (float*)d_out;

    const int M = in_sizes[6];   // 50000
    const int E = in_sizes[1];   // 1,600,000

    __half *A16, *H1, *H2, *W16;
    float *uvec, *dv, *ev;
    int *cnt, *rowptr, *cursor, *partial;
    int2 *edge;
    cudaGetSymbolAddress((void**)&A16, g_A16);
    cudaGetSymbolAddress((void**)&H1,  g_H1);
    cudaGetSymbolAddress((void**)&H2,  g_H2);
    cudaGetSymbolAddress((void**)&W16, g_W16);
    cudaGetSymbolAddress((void**)&uvec, g_uvec);
    cudaGetSymbolAddress((void**)&dv,   g_d);
    cudaGetSymbolAddress((void**)&ev,   g_e);
    cudaGetSymbolAddress((void**)&cnt,     g_cnt);
    cudaGetSymbolAddress((void**)&rowptr,  g_rowptr);
    cudaGetSymbolAddress((void**)&cursor,  g_cursor);
    cudaGetSymbolAddress((void**)&partial, g_partial);
    cudaGetSymbolAddress((void**)&edge,    g_edge);

    cudaFuncSetAttribute(fusedAB,    cudaFuncAttributeMaxDynamicSharedMemorySize, GEMM_SMEM);
    cudaFuncSetAttribute(gemm_final, cudaFuncAttributeMaxDynamicSharedMemorySize, GEMM_SMEM);

    __half* Wp[3] = {W16, W16 + (size_t)DD * DD, W16 + (size_t)2 * DD * DD};
    __half* W2c = H2;                       // scratch (H2 free until fusedC)
    __half* W3t = H2 + (size_t)DD * DD;

    const int eblk = (E + 255) / 256;
    const size_t prep_total = (size_t)WN4 + (size_t)M * DD;
    const int PB = (int)((prep_total + 255) / 256);
    const int rsB = (M + 3) / 4;
    const int scanB = (M + SCB - 1) / SCB;

    // L0: zero cnt (cannot share a launch with hist: write/atomic race)
    cudaMemsetAsync(cnt, 0, (size_t)M * sizeof(int), 0);
    // L1: weight/input casts || hist
    prep_hist<<<PB + eblk, 256>>>(Lin1, W1, W2, W3, A1, W16, W2c, W3t, A16, M,
                                  adj_rows, cnt, E, PB);
    // L2-3: parallel scan
    scan_part<<<scanB, SCB>>>(cnt, rowptr, partial, M);
    scan_add2<<<scanB, SCB>>>(rowptr, cursor, partial, M, E, scanB);
    // L4: a0 GEMM + H1 GEMM || scatter || W23^T product (16 CTAs)
    fusedAB<<<2 * G1 + eblk + 16, 256, GEMM_SMEM>>>(
        A16, Wp[0], Wp[1], Lin1_b, b1, out + 512, H1, M,
        adj_rows, adj_cols, adj_vals, cursor, edge, E, eblk,
        W3t, W2c, Wp[2]);
    // L5: spmm_mix || rowsum_d
    fusedC<<<M + rsB, 128>>>(rowptr, edge, H1, out + 512, nvec, H2, dv, M);
    // L6: spmm #2 || spmv_e || uvec
    fusedD<<<M + rsB + 4, 128>>>(rowptr, edge, H2, H1, dv, ev, b2, W3, uvec, M);
    // L7: spmm #3
    spmm_csr_h<<<M, 128>>>(rowptr, edge, H1, A16);
    // L8: final GEMM: out[:,0:512) = t2 @ W23 + e⊗u + d⊗b3
    gemm_final<<<G1, 256, GEMM_SMEM>>>(A16, Wp[2], ev, uvec, dv, b3, out, M);
}

// round 17
// speedup vs baseline: 1.4524x; 1.0455x over previous
#include <cuda_runtime.h>
#include <cuda_fp16.h>
#include <cstdint>
#include <cstddef>

#define NN 50000
#define EE 1600000
#define DD 512

// ---------------------------------------------------------------------------
// Device scratch (no runtime alloc allowed)
// ---------------------------------------------------------------------------
__device__ __half g_A16[(size_t)NN * DD];
__device__ __half g_H1[(size_t)NN * DD];
__device__ __half g_H2[(size_t)NN * DD];   // also scratch for W2/W3^T fp16 casts
__device__ __half g_W16[(size_t)3 * DD * DD];
__device__ float  g_uvec[DD];
// CSR scratch
__device__ int   g_cnt[NN];
__device__ int   g_rowptr[NN + 1];
__device__ int   g_cursor[NN];
__device__ int   g_partial[256];
__device__ int2  g_edge[EE];
__device__ float g_d[NN];
__device__ float g_e[NN];

// ---------------------------------------------------------------------------
// Helpers
// ---------------------------------------------------------------------------
__device__ __forceinline__ uint32_t smem_to_u32(const void* p) {
    uint32_t a;
    asm("{ .reg .u64 t; cvta.to.shared.u64 t, %1; cvt.u32.u64 %0, t; }" : "=r"(a) : "l"(p));
    return a;
}

__device__ __forceinline__ void cp16(uint32_t dst, const void* src, bool valid) {
    int sz = valid ? 16 : 0;
    asm volatile("cp.async.cg.shared.global [%0], [%1], 16, %2;"
                 :: "r"(dst), "l"(src), "r"(sz) : "memory");
}
#define CP_COMMIT() asm volatile("cp.async.commit_group;" ::: "memory")
#define CP_WAIT(n)  asm volatile("cp.async.wait_group %0;" :: "n"(n) : "memory")

__device__ __forceinline__ void mma_f16(float* d, const uint32_t* a, const uint32_t* b) {
    asm volatile("mma.sync.aligned.m16n8k16.row.col.f32.f16.f16.f32 "
                 "{%0,%1,%2,%3}, {%4,%5,%6,%7}, {%8,%9}, {%0,%1,%2,%3};"
                 : "+f"(d[0]), "+f"(d[1]), "+f"(d[2]), "+f"(d[3])
                 : "r"(a[0]), "r"(a[1]), "r"(a[2]), "r"(a[3]), "r"(b[0]), "r"(b[1]));
}

__device__ __forceinline__ void ldsm_x4(uint32_t* r, uint32_t addr) {
    asm volatile("ldmatrix.sync.aligned.m8n8.x4.shared.b16 {%0,%1,%2,%3}, [%4];"
                 : "=r"(r[0]), "=r"(r[1]), "=r"(r[2]), "=r"(r[3]) : "r"(addr));
}
__device__ __forceinline__ void ldsm_x2(uint32_t* r, uint32_t addr) {
    asm volatile("ldmatrix.sync.aligned.m8n8.x2.shared.b16 {%0,%1}, [%2];"
                 : "=r"(r[0]), "=r"(r[1]) : "r"(addr));
}

// L2 cache policies via createpolicy
__device__ __forceinline__ uint64_t pol_evict_last() {
    uint64_t p;
    asm("createpolicy.fractional.L2::evict_last.b64 %0, 1.0;" : "=l"(p));
    return p;
}
__device__ __forceinline__ uint64_t pol_evict_first() {
    uint64_t p;
    asm("createpolicy.fractional.L2::evict_first.b64 %0, 1.0;" : "=l"(p));
    return p;
}

__device__ __forceinline__ uint2 ldg_gather(const __half* p, uint64_t pol) {
    uint2 v;
    asm volatile("ld.global.nc.L2::cache_hint.v2.u32 {%0,%1}, [%2], %3;"
                 : "=r"(v.x), "=r"(v.y) : "l"(p), "l"(pol));
    return v;
}
__device__ __forceinline__ float4 ldg_once_f4(const float* p, uint64_t pol) {
    float4 v;
    asm volatile("ld.global.L2::cache_hint.v4.f32 {%0,%1,%2,%3}, [%4], %5;"
                 : "=f"(v.x), "=f"(v.y), "=f"(v.z), "=f"(v.w) : "l"(p), "l"(pol));
    return v;
}
__device__ __forceinline__ void stg_resident(__half* p, uint2 v, uint64_t pol) {
    asm volatile("st.global.L2::cache_hint.v2.u32 [%0], {%1,%2}, %3;"
                 :: "l"(p), "r"(v.x), "r"(v.y), "l"(pol) : "memory");
}
__device__ __forceinline__ void stg_resident32(__half* p, uint32_t v, uint64_t pol) {
    asm volatile("st.global.L2::cache_hint.u32 [%0], %1, %2;"
                 :: "l"(p), "r"(v), "l"(pol) : "memory");
}

// ---------------------------------------------------------------------------
// GEMM CTA body (ldmatrix + fp16 mma, fp32 accum)
// 3-stage cp.async pipeline, ONE __syncthreads per kc-chunk.
// Epilogue modes: rowE -> rank-1; else bias -> bias add; else zero.
// ---------------------------------------------------------------------------
#define BK 32
#define NKC (DD / BK)                     // 16 chunks
#define RSTRIDE 20
#define TILE_WORDS (128 * RSTRIDE)
#define STAGE_WORDS (2 * TILE_WORDS)
#define STAGE_BYTES (STAGE_WORDS * 4)     // 20480
#define GEMM_SMEM (3 * STAGE_BYTES)       // 61440 bytes (3 stages)
#define NBY ((NN + 127) / 128)            // 391
#define G1  (4 * NBY)                     // CTAs per N=512 GEMM: 1564

__device__ __forceinline__ void gemm_load_stage(
    uint32_t sbase, int stage, const __half* A, const __half* B,
    int bm, int bn, int kc, int M, int tid)
{
    const uint32_t st = sbase + (uint32_t)stage * STAGE_BYTES;
    const int r0 = tid >> 2;
    const int r1 = r0 + 64;
    const int j  = tid & 3;
    const uint32_t d0 = st + (uint32_t)(r0 * RSTRIDE + j * 4) * 4;
    const uint32_t d1 = st + (uint32_t)(r1 * RSTRIDE + j * 4) * 4;
    const size_t koff = (size_t)kc * BK + j * 8;
    const bool v0 = (bm + r0) < M;
    const bool v1 = (bm + r1) < M;

    cp16(d0,                  A + (size_t)(bm + r0) * DD + koff, v0);
    cp16(d1,                  A + (size_t)(bm + r1) * DD + koff, v1);
    cp16(d0 + TILE_WORDS * 4, B + (size_t)(bn + r0) * DD + koff, true);
    cp16(d1 + TILE_WORDS * 4, B + (size_t)(bn + r1) * DD + koff, true);
}

__device__ void gemm_cta(
    int g, uint32_t* s,
    const __half* __restrict__ A, const __half* __restrict__ B,
    const float* __restrict__ bias,
    const float* __restrict__ rowE, const float* __restrict__ colU,
    const float* __restrict__ rowD, const float* __restrict__ colB3,
    float* __restrict__ C, __half* __restrict__ C16, int ldc, int M)
{
    const uint32_t sbase = smem_to_u32(s);
    const int tid  = threadIdx.x;
    const int warp = tid >> 5;
    const int lane = tid & 31;
    const int wm   = (warp & 1) * 64;
    const int wn   = (warp >> 1) * 32;
    const int grp  = lane >> 2;
    const int qd   = lane & 3;
    const int bm = (g >> 2) * 128;
    const int n0 = (g & 3) * 128;

    const int arow = wm + (lane & 15);
    const int acol = (lane >> 4) * 4;
    const int brow = wn + (lane & 7);
    const int bcol = ((lane >> 3) & 1) * 4;

    float acc[4][4][4];
    #pragma unroll
    for (int i = 0; i < 4; i++)
        #pragma unroll
        for (int j = 0; j < 4; j++)
            #pragma unroll
            for (int q = 0; q < 4; q++) acc[i][j][q] = 0.f;

    // Prologue: fill stages 0,1 (chunks 0,1)
    gemm_load_stage(sbase, 0, A, B, bm, n0, 0, M, tid);
    CP_COMMIT();
    gemm_load_stage(sbase, 1, A, B, bm, n0, 1, M, tid);
    CP_COMMIT();

    int stage = 0;
    #pragma unroll 1
    for (int kc = 0; kc < NKC; kc++) {
        // chunk kc resident (kc+1 may still be in flight)
        if (kc + 1 < NKC) { CP_WAIT(1); } else { CP_WAIT(0); }
        __syncthreads();

        const uint32_t As_b = sbase + (uint32_t)stage * STAGE_BYTES;
        const uint32_t Bs_b = As_b + TILE_WORDS * 4;

        #pragma unroll
        for (int ks = 0; ks < 2; ks++) {
            const int kw = ks * 8;
            uint32_t ah[4][4];
            #pragma unroll
            for (int mi = 0; mi < 4; mi++)
                ldsm_x4(ah[mi], As_b + (uint32_t)((arow + mi * 16) * RSTRIDE + kw + acol) * 4);
            #pragma unroll
            for (int nj = 0; nj < 4; nj++) {
                uint32_t bh[2];
                ldsm_x2(bh, Bs_b + (uint32_t)((brow + nj * 8) * RSTRIDE + kw + bcol) * 4);
                #pragma unroll
                for (int mi = 0; mi < 4; mi++)
                    mma_f16(acc[mi][nj], ah[mi], bh);
            }
        }

        // Issue chunk kc+2 into stage (kc+2)%3 (safe: != stages read at iters kc, kc+1;
        // no warp is still at iter kc-1 because all passed this iter's barrier).
        if (kc + 2 < NKC) {
            int ws = stage + 2; if (ws >= 3) ws -= 3;
            gemm_load_stage(sbase, ws, A, B, bm, n0, kc + 2, M, tid);
            CP_COMMIT();
        }
        stage = (stage + 1 == 3) ? 0 : stage + 1;
    }
    __syncthreads();

    const uint64_t pl = pol_evict_last();
    #pragma unroll
    for (int mi = 0; mi < 4; mi++) {
        const int gr = bm + wm + mi * 16 + grp;
        float e0 = 0.f, d0v = 0.f, e1 = 0.f, d1v = 0.f;
        if (rowE) {
            if (gr < M)     { e0 = rowE[gr];     d0v = rowD[gr]; }
            if (gr + 8 < M) { e1 = rowE[gr + 8]; d1v = rowD[gr + 8]; }
        }
        #pragma unroll
        for (int nj = 0; nj < 4; nj++) {
            const int gc = n0 + wn + nj * 8 + qd * 2;
            float2 add0, add1;
            if (rowE) {
                const float2 uu = *(const float2*)(colU + gc);
                const float2 b3 = *(const float2*)(colB3 + gc);
                add0 = make_float2(e0 * uu.x + d0v * b3.x, e0 * uu.y + d0v * b3.y);
                add1 = make_float2(e1 * uu.x + d1v * b3.x, e1 * uu.y + d1v * b3.y);
            } else if (bias) {
                const float2 bz = *(const float2*)(bias + gc);
                add0 = bz; add1 = bz;
            } else {
                add0 = make_float2(0.f, 0.f);
                add1 = make_float2(0.f, 0.f);
            }
            float2 o0 = {acc[mi][nj][0] + add0.x, acc[mi][nj][1] + add0.y};
            float2 o1 = {acc[mi][nj][2] + add1.x, acc[mi][nj][3] + add1.y};
            if (C16) {
                __half2 h0 = __float22half2_rn(o0);
                __half2 h1 = __float22half2_rn(o1);
                if (gr < M)
                    stg_resident32(C16 + (size_t)gr * ldc + gc, *(uint32_t*)&h0, pl);
                if (gr + 8 < M)
                    stg_resident32(C16 + (size_t)(gr + 8) * ldc + gc, *(uint32_t*)&h1, pl);
            } else {
                if (gr < M)     *(float2*)(C + (size_t)gr * ldc + gc) = o0;
                if (gr + 8 < M) *(float2*)(C + (size_t)(gr + 8) * ldc + gc) = o1;
            }
        }
    }
}

// ---------------------------------------------------------------------------
// fusedAB: a0-GEMM + H1-GEMM + scatter + W23^T-product CTAs in one grid
// ---------------------------------------------------------------------------
__global__ void __launch_bounds__(256, 2) fusedAB(
    const __half* __restrict__ A, const __half* __restrict__ B0,
    const __half* __restrict__ B1,
    const float* __restrict__ bias0, const float* __restrict__ bias1,
    float* __restrict__ C, __half* __restrict__ H1, int M,
    const int* __restrict__ rows, const int* __restrict__ cols,
    const float* __restrict__ vals, int* __restrict__ cursor,
    int2* __restrict__ edge, int E, int EB,
    const __half* __restrict__ W3t, const __half* __restrict__ W2c,
    __half* __restrict__ W23T)
{
    extern __shared__ uint32_t s[];
    const int bid = blockIdx.x;
    if (bid < G1) {
        gemm_cta(bid, s, A, B0, bias0,
                 nullptr, nullptr, nullptr, nullptr, C, nullptr, 1024, M);
    } else if (bid < 2 * G1) {
        gemm_cta(bid - G1, s, A, B1, bias1,
                 nullptr, nullptr, nullptr, nullptr, nullptr, H1, DD, M);
    } else if (bid < 2 * G1 + EB) {
        int e = (bid - 2 * G1) * 256 + threadIdx.x;
        if (e < E) {
            int r = rows[e];
            int p = atomicAdd(&cursor[r], 1);
            edge[p] = make_int2(cols[e], __float_as_int(vals[e]));
        }
    } else {
        gemm_cta(bid - 2 * G1 - EB, s, W3t, W2c, nullptr,
                 nullptr, nullptr, nullptr, nullptr, nullptr, W23T, DD, DD);
    }
}

// Final GEMM (standalone, rank-1 epilogue)
__global__ void __launch_bounds__(256, 2) gemm_final(
    const __half* __restrict__ A, const __half* __restrict__ B,
    const float* __restrict__ rowE, const float* __restrict__ colU,
    const float* __restrict__ rowD, const float* __restrict__ colB3,
    float* __restrict__ C, int M)
{
    extern __shared__ uint32_t s[];
    gemm_cta(blockIdx.x, s, A, B, nullptr, rowE, colU, rowD, colB3,
             C, nullptr, 1024, M);
}

// ---------------------------------------------------------------------------
// Parallel scan: scan_part + scan_add2
// ---------------------------------------------------------------------------
#define SCB 256

__global__ void __launch_bounds__(SCB) scan_part(
    const int* __restrict__ cnt, int* __restrict__ row_ptr,
    int* __restrict__ partial, int M)
{
    __shared__ int sm[SCB];
    const int tid = threadIdx.x;
    const int i = blockIdx.x * SCB + tid;
    int v = (i < M) ? cnt[i] : 0;
    sm[tid] = v;
    __syncthreads();
    #pragma unroll
    for (int off = 1; off < SCB; off <<= 1) {
        int t = (tid >= off) ? sm[tid - off] : 0;
        __syncthreads();
        sm[tid] += t;
        __syncthreads();
    }
    if (i < M) row_ptr[i] = sm[tid] - v;
    if (tid == SCB - 1) partial[blockIdx.x] = sm[tid];
}

__global__ void __launch_bounds__(SCB) scan_add2(
    int* __restrict__ row_ptr, int* __restrict__ cursor,
    const int* __restrict__ partial, int M, int E, int nblk)
{
    __shared__ int sm[SCB];
    __shared__ int ex[SCB];
    const int tid = threadIdx.x;
    int v = (tid < nblk) ? partial[tid] : 0;
    sm[tid] = v;
    __syncthreads();
    #pragma unroll
    for (int off = 1; off < SCB; off <<= 1) {
        int t = (tid >= off) ? sm[tid - off] : 0;
        __syncthreads();
        sm[tid] += t;
        __syncthreads();
    }
    ex[tid] = sm[tid] - v;
    __syncthreads();
    const int off_b = ex[blockIdx.x];
    const int i = blockIdx.x * SCB + tid;
    if (i < M) {
        int val = row_ptr[i] + off_b;
        row_ptr[i] = val;
        cursor[i]  = val;
    }
    if (i == 0) row_ptr[M] = E;
}

// ---------------------------------------------------------------------------
// fp16 CSR SpMM core: 4-edge unrolled, evict_last gathers, fp32 accum
// ---------------------------------------------------------------------------
__device__ __forceinline__ void fma_h4(float4& acc, float v, uint2 r) {
    const float2 a0 = __half22float2(*(const __half2*)&r.x);
    const float2 a1 = __half22float2(*(const __half2*)&r.y);
    acc.x = fmaf(v, a0.x, acc.x); acc.y = fmaf(v, a0.y, acc.y);
    acc.z = fmaf(v, a1.x, acc.z); acc.w = fmaf(v, a1.y, acc.w);
}

__device__ __forceinline__ float4 spmm_row_acc_h(
    const int* __restrict__ row_ptr, const int2* __restrict__ edge,
    const __half* __restrict__ in, int r, int tid, uint64_t pol)
{
    const size_t off = (size_t)tid * 4;
    int e = row_ptr[r];
    const int end = row_ptr[r + 1];
    float4 acc = {0.f, 0.f, 0.f, 0.f};

    for (; e + 4 <= end; e += 4) {
        const int2 E0 = __ldg(edge + e);
        const int2 E1 = __ldg(edge + e + 1);
        const int2 E2 = __ldg(edge + e + 2);
        const int2 E3 = __ldg(edge + e + 3);
        const uint2 R0 = ldg_gather(in + (size_t)E0.x * DD + off, pol);
        const uint2 R1 = ldg_gather(in + (size_t)E1.x * DD + off, pol);
        const uint2 R2 = ldg_gather(in + (size_t)E2.x * DD + off, pol);
        const uint2 R3 = ldg_gather(in + (size_t)E3.x * DD + off, pol);
        fma_h4(acc, __int_as_float(E0.y), R0);
        fma_h4(acc, __int_as_float(E1.y), R1);
        fma_h4(acc, __int_as_float(E2.y), R2);
        fma_h4(acc, __int_as_float(E3.y), R3);
    }
    for (; e < end; e++) {
        const int2 E0 = __ldg(edge + e);
        const uint2 R0 = ldg_gather(in + (size_t)E0.x * DD + off, pol);
        fma_h4(acc, __int_as_float(E0.y), R0);
    }
    return acc;
}

__device__ __forceinline__ uint2 pack_h4(float4 v) {
    uint2 o;
    *(__half2*)&o.x = __float22half2_rn(make_float2(v.x, v.y));
    *(__half2*)&o.y = __float22half2_rn(make_float2(v.z, v.w));
    return o;
}

// fusedC: spmm_mix || rowsum_d
__global__ void __launch_bounds__(128) fusedC(
    const int* __restrict__ row_ptr, const int2* __restrict__ edge,
    const __half* __restrict__ in,
    const float* __restrict__ a0, const float* __restrict__ nvec,
    __half* __restrict__ x1, float* __restrict__ dvec, int M)
{
    const int bid = blockIdx.x;
    const int tid = threadIdx.x;
    if (bid < M) {
        const uint64_t pl = pol_evict_last();
        const uint64_t pf = pol_evict_first();
        float4 acc = spmm_row_acc_h(row_ptr, edge, in, bid, tid, pl);
        const float nv = nvec[bid];
        const float om = 1.f - nv;
        const float4 a = ldg_once_f4(a0 + (size_t)bid * 1024 + (size_t)tid * 4, pf);
        float4 o;
        o.x = a.x * nv + acc.x * om;
        o.y = a.y * nv + acc.y * om;
        o.z = a.z * nv + acc.z * om;
        o.w = a.w * nv + acc.w * om;
        stg_resident(x1 + (size_t)bid * DD + (size_t)tid * 4, pack_h4(o), pl);
    } else {
        const int r = (bid - M) * 4 + (tid >> 5);
        if (r >= M) return;
        const int lane = tid & 31;
        float acc = 0.f;
        for (int e = row_ptr[r] + lane; e < row_ptr[r + 1]; e += 32)
            acc += __int_as_float(__ldg(&edge[e].y));
        #pragma unroll
        for (int o = 16; o; o >>= 1) acc += __shfl_down_sync(0xffffffffu, acc, o);
        if (lane == 0) dvec[r] = acc;
    }
}

// fusedD: spmm (H1 = S·H2) || spmv_e || uvec
__global__ void __launch_bounds__(128) fusedD(
    const int* __restrict__ row_ptr, const int2* __restrict__ edge,
    const __half* __restrict__ in, __half* __restrict__ out,
    const float* __restrict__ dvec, float* __restrict__ evec,
    const float* __restrict__ b2, const float* __restrict__ W3,
    float* __restrict__ u, int M)
{
    const int bid = blockIdx.x;
    const int tid = threadIdx.x;
    const int UB = M + (M + 3) / 4;
    if (bid < M) {
        const uint64_t pl = pol_evict_last();
        float4 acc = spmm_row_acc_h(row_ptr, edge, in, bid, tid, pl);
        stg_resident(out + (size_t)bid * DD + (size_t)tid * 4, pack_h4(acc), pl);
    } else if (bid < UB) {
        const int r = (bid - M) * 4 + (tid >> 5);
        if (r >= M) return;
        const int lane = tid & 31;
        float acc = 0.f;
        for (int e = row_ptr[r] + lane; e < row_ptr[r + 1]; e += 32) {
            const int2 ev2 = __ldg(edge + e);
            acc = fmaf(__int_as_float(ev2.y), dvec[ev2.x], acc);
        }
        #pragma unroll
        for (int o = 16; o; o >>= 1) acc += __shfl_down_sync(0xffffffffu, acc, o);
        if (lane == 0) evec[r] = acc;
    } else {
        const int n = (bid - UB) * 128 + tid;
        float acc = 0.f;
        #pragma unroll 8
        for (int j = 0; j < DD; j++)
            acc = fmaf(b2[j], W3[j * DD + n], acc);
        u[n] = acc;
    }
}

// Plain fp16 SpMM (#3)
__global__ void __launch_bounds__(128) spmm_csr_h(
    const int* __restrict__ row_ptr, const int2* __restrict__ edge,
    const __half* __restrict__ in, __half* __restrict__ out)
{
    const uint64_t pl = pol_evict_last();
    float4 acc = spmm_row_acc_h(row_ptr, edge, in, blockIdx.x, threadIdx.x, pl);
    uint2 o = pack_h4(acc);
    *(uint2*)(out + (size_t)blockIdx.x * DD + (size_t)threadIdx.x * 4) = o;
}

// ---------------------------------------------------------------------------
// L1: prep (4 weight casts + A16 split) || hist
// ---------------------------------------------------------------------------
#define WN4 (4 * DD * DD)
__global__ void __launch_bounds__(256) prep_hist(
    const float* __restrict__ Lin1, const float* __restrict__ W1,
    const float* __restrict__ W2,   const float* __restrict__ W3,
    const float* __restrict__ A1,
    __half* __restrict__ W16, __half* __restrict__ W2c,
    __half* __restrict__ W3t, __half* __restrict__ A16, int M,
    const int* __restrict__ rows, int* __restrict__ cnt, int E, int PB)
{
    const int bid = blockIdx.x;
    if (bid < PB) {
        size_t i = (size_t)bid * 256 + threadIdx.x;
        if (i < WN4) {
            int w = (int)(i / (DD * DD));
            int j = (int)(i % (DD * DD));
            int n = j >> 9, k = j & 511;
            if (w == 0)      W16[j]            = __float2half_rn(Lin1[k * DD + n]);
            else if (w == 1) W16[DD * DD + j]  = __float2half_rn(W1[k * DD + n]);
            else if (w == 2) W2c[j]            = __float2half_rn(W2[j]);
            else             W3t[j]            = __float2half_rn(W3[k * DD + n]);
            return;
        }
        size_t j = i - WN4;
        if (j < (size_t)M * DD) {
            size_t r = j >> 9;
            int c = (int)(j & 511);
            A16[j] = __float2half_rn(A1[r * 513 + 1 + c]);
        }
    } else {
        int e = (bid - PB) * 256 + threadIdx.x;
        if (e < E) atomicAdd(&cnt[rows[e]], 1);
    }
}

// ---------------------------------------------------------------------------
// Host driver
// ---------------------------------------------------------------------------
extern "C" void kernel_launch(void* const* d_in, const int* in_sizes, int n_in,
                              void* d_out, int out_size)
{
    const float* A1       = (const float*)d_in[0];
    const int*   adj_rows = (const int*)  d_in[1];
    const int*   adj_cols = (const int*)  d_in[2];
    const float* adj_vals = (const float*)d_in[3];
    const float* Lin1     = (const float*)d_in[4];
    const float* Lin1_b   = (const float*)d_in[5];
    const float* nvec     = (const float*)d_in[6];
    const float* W1       = (const float*)d_in[7];
    const float* b1       = (const float*)d_in[8];
    const float* W2       = (const float*)d_in[9];
    const float* b2       = (const float*)d_in[10];
    const float* W3       = (const float*)d_in[11];
    const float* b3       = (const float*)d_in[12];
    float* out = (float*)d_out;

    const int M = in_sizes[6];   // 50000
    const int E = in_sizes[1];   // 1,600,000

    __half *A16, *H1, *H2, *W16;
    float *uvec, *dv, *ev;
    int *cnt, *rowptr, *cursor, *partial;
    int2 *edge;
    cudaGetSymbolAddress((void**)&A16, g_A16);
    cudaGetSymbolAddress((void**)&H1,  g_H1);
    cudaGetSymbolAddress((void**)&H2,  g_H2);
    cudaGetSymbolAddress((void**)&W16, g_W16);
    cudaGetSymbolAddress((void**)&uvec, g_uvec);
    cudaGetSymbolAddress((void**)&dv,   g_d);
    cudaGetSymbolAddress((void**)&ev,   g_e);
    cudaGetSymbolAddress((void**)&cnt,     g_cnt);
    cudaGetSymbolAddress((void**)&rowptr,  g_rowptr);
    cudaGetSymbolAddress((void**)&cursor,  g_cursor);
    cudaGetSymbolAddress((void**)&partial, g_partial);
    cudaGetSymbolAddress((void**)&edge,    g_edge);

    cudaFuncSetAttribute(fusedAB,    cudaFuncAttributeMaxDynamicSharedMemorySize, GEMM_SMEM);
    cudaFuncSetAttribute(gemm_final, cudaFuncAttributeMaxDynamicSharedMemorySize, GEMM_SMEM);

    __half* Wp[3] = {W16, W16 + (size_t)DD * DD, W16 + (size_t)2 * DD * DD};
    __half* W2c = H2;
    __half* W3t = H2 + (size_t)DD * DD;

    const int eblk = (E + 255) / 256;
    const size_t prep_total = (size_t)WN4 + (size_t)M * DD;
    const int PB = (int)((prep_total + 255) / 256);
    const int rsB = (M + 3) / 4;
    const int scanB = (M + SCB - 1) / SCB;

    // L0: zero cnt
    cudaMemsetAsync(cnt, 0, (size_t)M * sizeof(int), 0);
    // L1: weight/input casts || hist
    prep_hist<<<PB + eblk, 256>>>(Lin1, W1, W2, W3, A1, W16, W2c, W3t, A16, M,
                                  adj_rows, cnt, E, PB);
    // L2-3: parallel scan
    scan_part<<<scanB, SCB>>>(cnt, rowptr, partial, M);
    scan_add2<<<scanB, SCB>>>(rowptr, cursor, partial, M, E, scanB);
    // L4: a0 GEMM + H1 GEMM || scatter || W23^T product
    fusedAB<<<2 * G1 + eblk + 16, 256, GEMM_SMEM>>>(
        A16, Wp[0], Wp[1], Lin1_b, b1, out + 512, H1, M,
        adj_rows, adj_cols, adj_vals, cursor, edge, E, eblk,
        W3t, W2c, Wp[2]);
    // L5: spmm_mix || rowsum_d
    fusedC<<<M + rsB, 128>>>(rowptr, edge, H1, out + 512, nvec, H2, dv, M);
    // L6: spmm #2 || spmv_e || uvec
    fusedD<<<M + rsB + 4, 128>>>(rowptr, edge, H2, H1, dv, ev, b2, W3, uvec, M);
    // L7: spmm #3
    spmm_csr_h<<<M, 128>>>(rowptr, edge, H1, A16);
    // L8: final GEMM: out[:,0:512) = t2 @ W23 + e⊗u + d⊗b3
    gemm_final<<<G1, 256, GEMM_SMEM>>>(A16, Wp[2], ev, uvec, dv, b3, out, M);
}